// round 2
// baseline (speedup 1.0000x reference)
#include <cuda_runtime.h>

#define NN   2048
#define BB   32
#define II   32
#define OO   32
#define SS   12
#define EE   16
#define KK   3          // K+1 hops
#define BIS  12288      // B*II*SS
#define PW   (KK*II*OO) // 3072 per-node weight elems

// ---------------- scratch (device globals; no allocations allowed) ----------
__device__ float g_h1[II * NN];
__device__ float g_h2[II * EE];
__device__ float g_m[EE * EE];
__device__ float g_A[(size_t)NN * NN];
__device__ float g_Xt[(size_t)NN * BIS];
__device__ float g_Y1[(size_t)NN * BIS];
__device__ float g_Y2[(size_t)NN * BIS];
__device__ float g_W[(size_t)NN * PW];
__device__ float g_bias[NN * OO];

// ---------------- 1. h1[i,n] = tanh(x[0,i,n,:] . fc0_w + fc0_b) -------------
__global__ void k_h1(const float* __restrict__ x,
                     const float* __restrict__ fc0w,
                     const float* __restrict__ fc0b) {
    int idx = blockIdx.x * 256 + threadIdx.x;       // i*NN + n  (b = 0 plane)
    float acc = fc0b[0];
    const float* xr = x + (size_t)idx * SS;
#pragma unroll
    for (int s = 0; s < SS; ++s) acc = fmaf(xr[s], fc0w[s], acc);
    g_h1[idx] = tanhf(acc);
}

// ---------------- 2. h2[i,d] = tanh(h1[i,:] . fc1_w[d,:] + fc1_b[d]) --------
__global__ void k_h2(const float* __restrict__ fc1w,
                     const float* __restrict__ fc1b) {
    int i = blockIdx.x >> 4;
    int d = blockIdx.x & 15;
    int tid = threadIdx.x;
    float p = 0.f;
    for (int n = tid; n < NN; n += 256)
        p = fmaf(g_h1[i * NN + n], fc1w[d * NN + n], p);
    __shared__ float red[256];
    red[tid] = p; __syncthreads();
    for (int st = 128; st > 0; st >>= 1) {
        if (tid < st) red[tid] += red[tid + st];
        __syncthreads();
    }
    if (tid == 0) g_h2[i * EE + d] = tanhf(red[0] + fc1b[d]);
}

// ---------------- 3. m[d,e] = tanh(sum_i h2[i,d]*fc2_w[e,i] + fc2_b[e]) -----
__global__ void k_m(const float* __restrict__ fc2w,
                    const float* __restrict__ fc2b) {
    int t = threadIdx.x;            // 256 = EE*EE
    int d = t >> 4, e = t & 15;
    float acc = fc2b[e];
#pragma unroll
    for (int i = 0; i < II; ++i) acc = fmaf(g_h2[i * EE + d], fc2w[e * II + i], acc);
    g_m[d * EE + e] = tanhf(acc);
}

// ------- 4. A[n,:] = softmax_m( relu( (E1[n]·m) · E2[m]ᵀ ) ) ----------------
// ReLU guarantees logits >= 0, so row-max init at 0 is exact.
__global__ void k_adj(const float* __restrict__ E1,
                      const float* __restrict__ E2) {
    int n = blockIdx.x;
    int tid = threadIdx.x;
    __shared__ float msm[EE * EE];
    __shared__ float psh[EE];
    __shared__ float buf[NN];
    __shared__ float red[256];
    msm[tid] = g_m[tid];
    __syncthreads();
    if (tid < EE) {
        float a = 0.f;
#pragma unroll
        for (int d = 0; d < EE; ++d) a = fmaf(E1[n * EE + d], msm[d * EE + tid], a);
        psh[tid] = a;
    }
    __syncthreads();
    float pl[EE];
#pragma unroll
    for (int e = 0; e < EE; ++e) pl[e] = psh[e];

    float lmax = 0.f;
    for (int mc = tid; mc < NN; mc += 256) {
        const float* er = E2 + mc * EE;
        float a = 0.f;
#pragma unroll
        for (int e = 0; e < EE; ++e) a = fmaf(pl[e], er[e], a);
        a = fmaxf(a, 0.f);
        buf[mc] = a;
        lmax = fmaxf(lmax, a);
    }
    red[tid] = lmax; __syncthreads();
    for (int st = 128; st > 0; st >>= 1) {
        if (tid < st) red[tid] = fmaxf(red[tid], red[tid + st]);
        __syncthreads();
    }
    lmax = red[0];
    __syncthreads();

    float lsum = 0.f;
    for (int mc = tid; mc < NN; mc += 256) {
        float v = __expf(buf[mc] - lmax);
        buf[mc] = v;
        lsum += v;
    }
    red[tid] = lsum; __syncthreads();
    for (int st = 128; st > 0; st >>= 1) {
        if (tid < st) red[tid] += red[tid + st];
        __syncthreads();
    }
    float inv = 1.0f / red[0];
    for (int mc = tid; mc < NN; mc += 256)
        g_A[(size_t)n * NN + mc] = buf[mc] * inv;
}

// ---------------- 5. Xt[m, (b,i,s)] = x[b,i,m,s] ----------------------------
__global__ void k_transpose(const float* __restrict__ x) {
    int idx = blockIdx.x * 256 + threadIdx.x;       // m*1024 + bi
    int m  = idx >> 10;
    int bi = idx & 1023;
    const float* src = x + ((size_t)bi * NN + m) * SS;
    float* dst = g_Xt + (size_t)m * BIS + bi * SS;
#pragma unroll
    for (int s = 0; s < SS; ++s) dst[s] = src[s];
}

// ---------------- 6. SGEMM  C[2048,12288] = g_A[2048,2048] * B ---------------
#define BMg 128
#define BNg 128
#define BKg 16
__global__ __launch_bounds__(256) void k_sgemm(int sel) {
    const float* __restrict__ A = g_A;
    const float* __restrict__ B = sel ? g_Y1 : g_Xt;
    float* __restrict__ C       = sel ? g_Y2 : g_Y1;
    __shared__ float As[BKg][BMg];
    __shared__ float Bs[BKg][BNg];
    int tid = threadIdx.x;
    int tx = tid & 15, ty = tid >> 4;
    size_t aBase = (size_t)blockIdx.y * BMg * NN;
    size_t col0  = (size_t)blockIdx.x * BNg;
    int aRow = tid >> 2;
    int aCol = (tid & 3) << 2;
    int bRow = tid >> 5;
    int bCol = (tid & 31) << 2;
    float acc[8][8] = {};
    for (int k0 = 0; k0 < NN; k0 += BKg) {
#pragma unroll
        for (int r = 0; r < 2; ++r) {
            float4 v = *(const float4*)(A + aBase + (size_t)(aRow + r * 64) * NN + k0 + aCol);
            As[aCol + 0][aRow + r * 64] = v.x;
            As[aCol + 1][aRow + r * 64] = v.y;
            As[aCol + 2][aRow + r * 64] = v.z;
            As[aCol + 3][aRow + r * 64] = v.w;
        }
#pragma unroll
        for (int r = 0; r < 2; ++r) {
            float4 v = *(const float4*)(B + (size_t)(k0 + bRow + r * 8) * BIS + col0 + bCol);
            *(float4*)&Bs[bRow + r * 8][bCol] = v;
        }
        __syncthreads();
#pragma unroll
        for (int kk = 0; kk < BKg; ++kk) {
            float ar[8], br[8];
#pragma unroll
            for (int i = 0; i < 8; ++i) ar[i] = As[kk][ty * 8 + i];
#pragma unroll
            for (int j = 0; j < 8; ++j) br[j] = Bs[kk][tx * 8 + j];
#pragma unroll
            for (int i = 0; i < 8; ++i)
#pragma unroll
                for (int j = 0; j < 8; ++j)
                    acc[i][j] = fmaf(ar[i], br[j], acc[i][j]);
        }
        __syncthreads();
    }
#pragma unroll
    for (int i = 0; i < 8; ++i) {
        size_t row = (size_t)blockIdx.y * BMg + ty * 8 + i;
        float* cp = C + row * BIS + col0 + tx * 8;
#pragma unroll
        for (int j = 0; j < 8; j += 4) {
            float4 v = make_float4(acc[i][j], acc[i][j + 1], acc[i][j + 2], acc[i][j + 3]);
            *(float4*)(cp + j) = v;
        }
    }
}

// ---------------- 7. per-node generated weights + bias ----------------------
__global__ void k_weights(const float* __restrict__ E1, const float* __restrict__ E2,
                          const float* __restrict__ Wp, const float* __restrict__ Wp2,
                          const float* __restrict__ bp, const float* __restrict__ bp2) {
    int n = blockIdx.x, tid = threadIdx.x;
    __shared__ float e1[EE], e2[EE];
    if (tid < EE) e1[tid] = E1[n * EE + tid];
    else if (tid < 2 * EE) e2[tid - EE] = E2[n * EE + tid - EE];
    __syncthreads();
    float l1[EE], l2[EE];
#pragma unroll
    for (int d = 0; d < EE; ++d) { l1[d] = e1[d]; l2[d] = e2[d]; }
    for (int q = tid; q < PW; q += 256) {
        float acc = 0.f;
#pragma unroll
        for (int d = 0; d < EE; ++d)
            acc = fmaf(l1[d], Wp[d * PW + q], fmaf(l2[d], Wp2[d * PW + q], acc));
        g_W[(size_t)n * PW + q] = acc;
    }
    if (tid < OO) {
        float acc = 0.f;
#pragma unroll
        for (int d = 0; d < EE; ++d)
            acc = fmaf(l1[d], bp[d * OO + tid], fmaf(l2[d], bp2[d * OO + tid], acc));
        g_bias[n * OO + tid] = acc;
    }
}

// -------- 8. out[b,o,n,s] = sum_{k,i} Yk[n,b,i,s] * W[n,k,i,o] + bias[n,o] --
__global__ __launch_bounds__(384) void k_gconv(float* __restrict__ out) {
    int n = blockIdx.x, tid = threadIdx.x;          // 384 threads = (b,s)
    __shared__ float Ws[PW];
    __shared__ float bsh[OO];
    for (int q = tid; q < PW; q += 384) Ws[q] = g_W[(size_t)n * PW + q];
    if (tid < OO) bsh[tid] = g_bias[n * OO + tid];
    __syncthreads();
    int b = tid / SS, s = tid - b * SS;
    float acc[OO];
#pragma unroll
    for (int o = 0; o < OO; ++o) acc[o] = bsh[o];
    const float* Yb[3] = { g_Xt, g_Y1, g_Y2 };
#pragma unroll
    for (int k = 0; k < KK; ++k) {
        const float* yb = Yb[k] + (size_t)n * BIS + (size_t)b * II * SS + s;
        const float* wk = Ws + k * II * OO;
#pragma unroll 4
        for (int i = 0; i < II; ++i) {
            float v = yb[i * SS];
            const float* wr = wk + i * OO;
#pragma unroll
            for (int o = 0; o < OO; ++o) acc[o] = fmaf(v, wr[o], acc[o]);
        }
    }
#pragma unroll
    for (int o = 0; o < OO; ++o)
        out[(((size_t)b * OO + o) * NN + n) * SS + s] = acc[o];
}

// ---------------------------------------------------------------------------
extern "C" void kernel_launch(void* const* d_in, const int* in_sizes, int n_in,
                              void* d_out, int out_size) {
    const float* x    = (const float*)d_in[0];
    const float* E1   = (const float*)d_in[1];
    const float* E2   = (const float*)d_in[2];
    const float* Wp   = (const float*)d_in[3];
    const float* Wp2  = (const float*)d_in[4];
    const float* bp   = (const float*)d_in[5];
    const float* bp2  = (const float*)d_in[6];
    const float* fc0w = (const float*)d_in[7];
    const float* fc0b = (const float*)d_in[8];
    const float* fc1w = (const float*)d_in[9];
    const float* fc1b = (const float*)d_in[10];
    const float* fc2w = (const float*)d_in[11];
    const float* fc2b = (const float*)d_in[12];
    float* out = (float*)d_out;

    k_h1<<<II * NN / 256, 256>>>(x, fc0w, fc0b);
    k_h2<<<II * EE, 256>>>(fc1w, fc1b);
    k_m<<<1, 256>>>(fc2w, fc2b);
    k_adj<<<NN, 256>>>(E1, E2);
    k_transpose<<<NN * 1024 / 256, 256>>>(x);
    dim3 gg(BIS / BNg, NN / BMg);
    k_sgemm<<<gg, 256>>>(0);     // Y1 = S @ Xt
    k_sgemm<<<gg, 256>>>(1);     // Y2 = S @ Y1  (== S^2 @ Xt)
    k_weights<<<NN, 256>>>(E1, E2, Wp, Wp2, bp, bp2);
    k_gconv<<<NN, 384>>>(out);
}

// round 6
// speedup vs baseline: 2.0522x; 2.0522x over previous
#include <cuda_runtime.h>
#include <cuda_bf16.h>
#include <cstdint>

#define NN   2048
#define BB   32
#define II   32
#define OO   32
#define SS   12
#define EE   16
#define KK   3          // K+1 hops
#define BIS  12288      // B*II*SS
#define PW   (KK*II*OO)

// ---------------- scratch (device globals) ----------------------------------
__device__ float g_h1[II * NN];
__device__ float g_h2[II * EE];
__device__ float g_m[EE * EE];
__device__ float g_Xt[(size_t)NN * BIS];
__device__ float g_Y1[(size_t)NN * BIS];
__device__ float g_Y2[(size_t)NN * BIS];
__device__ float g_W[(size_t)NN * PW];
__device__ float g_bias[NN * OO];
// bf16 split operands (16B-aligned for cp.async.16)
__device__ __align__(16) __nv_bfloat16 g_Ah[(size_t)NN * NN];
__device__ __align__(16) __nv_bfloat16 g_Al[(size_t)NN * NN];
__device__ __align__(16) __nv_bfloat16 g_B0h[(size_t)BIS * NN];
__device__ __align__(16) __nv_bfloat16 g_B0l[(size_t)BIS * NN];
__device__ __align__(16) __nv_bfloat16 g_B1h[(size_t)BIS * NN];
__device__ __align__(16) __nv_bfloat16 g_B1l[(size_t)BIS * NN];

// ---------------- helpers ----------------------------------------------------
__device__ __forceinline__ uint32_t smem_u32(const void* p) {
    uint32_t a;
    asm("{ .reg .u64 t; cvta.to.shared.u64 t, %1; cvt.u32.u64 %0, t; }" : "=r"(a) : "l"(p));
    return a;
}
__device__ __forceinline__ void cp16(uint32_t dst, const void* src) {
    asm volatile("cp.async.cg.shared.global [%0], [%1], 16;" :: "r"(dst), "l"(src) : "memory");
}
#define CP_COMMIT() asm volatile("cp.async.commit_group;" ::: "memory")
#define CP_WAIT1()  asm volatile("cp.async.wait_group 1;" ::: "memory")
#define CP_WAIT0()  asm volatile("cp.async.wait_group 0;" ::: "memory")

__device__ __forceinline__ void ldsm4(uint32_t* r, uint32_t addr) {
    asm volatile("ldmatrix.sync.aligned.m8n8.x4.shared.b16 {%0,%1,%2,%3}, [%4];"
                 : "=r"(r[0]), "=r"(r[1]), "=r"(r[2]), "=r"(r[3]) : "r"(addr));
}
__device__ __forceinline__ void ldsm2(uint32_t* r, uint32_t addr) {
    asm volatile("ldmatrix.sync.aligned.m8n8.x2.shared.b16 {%0,%1}, [%2];"
                 : "=r"(r[0]), "=r"(r[1]) : "r"(addr));
}
__device__ __forceinline__ void mma16816(float* c, const uint32_t* a, const uint32_t* b) {
    asm volatile(
        "mma.sync.aligned.m16n8k16.row.col.f32.bf16.bf16.f32 "
        "{%0,%1,%2,%3}, {%4,%5,%6,%7}, {%8,%9}, {%0,%1,%2,%3};"
        : "+f"(c[0]), "+f"(c[1]), "+f"(c[2]), "+f"(c[3])
        : "r"(a[0]), "r"(a[1]), "r"(a[2]), "r"(a[3]), "r"(b[0]), "r"(b[1]));
}

// ---------------- 1. h1 -----------------------------------------------------
__global__ void k_h1(const float* __restrict__ x,
                     const float* __restrict__ fc0w,
                     const float* __restrict__ fc0b) {
    int idx = blockIdx.x * 256 + threadIdx.x;
    float acc = fc0b[0];
    const float* xr = x + (size_t)idx * SS;
#pragma unroll
    for (int s = 0; s < SS; ++s) acc = fmaf(xr[s], fc0w[s], acc);
    g_h1[idx] = tanhf(acc);
}

// ---------------- 2. h2 -----------------------------------------------------
__global__ void k_h2(const float* __restrict__ fc1w,
                     const float* __restrict__ fc1b) {
    int i = blockIdx.x >> 4;
    int d = blockIdx.x & 15;
    int tid = threadIdx.x;
    float p = 0.f;
    for (int n = tid; n < NN; n += 256)
        p = fmaf(g_h1[i * NN + n], fc1w[d * NN + n], p);
    __shared__ float red[256];
    red[tid] = p; __syncthreads();
    for (int st = 128; st > 0; st >>= 1) {
        if (tid < st) red[tid] += red[tid + st];
        __syncthreads();
    }
    if (tid == 0) g_h2[i * EE + d] = tanhf(red[0] + fc1b[d]);
}

// ---------------- 3. m ------------------------------------------------------
__global__ void k_m(const float* __restrict__ fc2w,
                    const float* __restrict__ fc2b) {
    int t = threadIdx.x;
    int d = t >> 4, e = t & 15;
    float acc = fc2b[e];
#pragma unroll
    for (int i = 0; i < II; ++i) acc = fmaf(g_h2[i * EE + d], fc2w[e * II + i], acc);
    g_m[d * EE + e] = tanhf(acc);
}

// ------- 4. adjacency softmax -> bf16 split ---------------------------------
__global__ void k_adj(const float* __restrict__ E1,
                      const float* __restrict__ E2) {
    int n = blockIdx.x;
    int tid = threadIdx.x;
    __shared__ float msm[EE * EE];
    __shared__ float psh[EE];
    __shared__ float buf[NN];
    __shared__ float red[256];
    msm[tid] = g_m[tid];
    __syncthreads();
    if (tid < EE) {
        float a = 0.f;
#pragma unroll
        for (int d = 0; d < EE; ++d) a = fmaf(E1[n * EE + d], msm[d * EE + tid], a);
        psh[tid] = a;
    }
    __syncthreads();
    float pl[EE];
#pragma unroll
    for (int e = 0; e < EE; ++e) pl[e] = psh[e];

    float lmax = 0.f;   // relu => logits >= 0
    for (int mc = tid; mc < NN; mc += 256) {
        const float* er = E2 + mc * EE;
        float a = 0.f;
#pragma unroll
        for (int e = 0; e < EE; ++e) a = fmaf(pl[e], er[e], a);
        a = fmaxf(a, 0.f);
        buf[mc] = a;
        lmax = fmaxf(lmax, a);
    }
    red[tid] = lmax; __syncthreads();
    for (int st = 128; st > 0; st >>= 1) {
        if (tid < st) red[tid] = fmaxf(red[tid], red[tid + st]);
        __syncthreads();
    }
    lmax = red[0];
    __syncthreads();

    float lsum = 0.f;
    for (int mc = tid; mc < NN; mc += 256) {
        float v = __expf(buf[mc] - lmax);
        buf[mc] = v;
        lsum += v;
    }
    red[tid] = lsum; __syncthreads();
    for (int st = 128; st > 0; st >>= 1) {
        if (tid < st) red[tid] += red[tid + st];
        __syncthreads();
    }
    float inv = 1.0f / red[0];
    for (int mc = tid; mc < NN; mc += 256) {
        float v = buf[mc] * inv;
        __nv_bfloat16 h = __float2bfloat16(v);
        __nv_bfloat16 l = __float2bfloat16(v - __bfloat162float(h));
        g_Ah[(size_t)n * NN + mc] = h;
        g_Al[(size_t)n * NN + mc] = l;
    }
}

// ---------------- 5. Xt transpose -------------------------------------------
__global__ void k_transpose(const float* __restrict__ x) {
    int idx = blockIdx.x * 256 + threadIdx.x;
    int m  = idx >> 10;
    int bi = idx & 1023;
    const float* src = x + ((size_t)bi * NN + m) * SS;
    float* dst = g_Xt + (size_t)m * BIS + bi * SS;
#pragma unroll
    for (int s = 0; s < SS; ++s) dst[s] = src[s];
}

// --------- 5b. transpose+split: [2048,12288]f32 -> [12288,2048] bf16 h/l ----
// which=0: g_Xt -> g_B0h/l     which=1: g_Y1 -> g_B1h/l
// (globals referenced from DEVICE code only -- host-side symbol decay is UB)
__global__ __launch_bounds__(256) void k_splitT(int which) {
    const float* __restrict__ src = which ? g_Y1 : g_Xt;
    __nv_bfloat16* __restrict__ dh = which ? g_B1h : g_B0h;
    __nv_bfloat16* __restrict__ dl = which ? g_B1l : g_B0l;
    __shared__ float t[32][33];
    int tx = threadIdx.x & 31, ty = threadIdx.x >> 5;
    int c0 = blockIdx.x * 32;
    int k0 = blockIdx.y * 32;
#pragma unroll
    for (int j = 0; j < 32; j += 8)
        t[ty + j][tx] = src[(size_t)(k0 + ty + j) * BIS + c0 + tx];
    __syncthreads();
#pragma unroll
    for (int j = 0; j < 32; j += 8) {
        float v = t[tx][ty + j];
        __nv_bfloat16 h = __float2bfloat16(v);
        __nv_bfloat16 l = __float2bfloat16(v - __bfloat162float(h));
        size_t o = (size_t)(c0 + ty + j) * NN + k0 + tx;
        dh[o] = h;
        dl[o] = l;
    }
}

// ============== 6. mma.sync GEMM  C[2048,12288] = S @ X =====================
// BM=128, BN=128, BK=32; smem rows padded to 80B; 3-stage cp.async pipeline.
#define ROWB 80
#define MATSZ (128 * ROWB)      // 10240 B per matrix tile
#define STG   (4 * MATSZ)       // Ah, Al, Bh, Bl
#define NSTG  3
#define SMTOT (NSTG * STG)      // 122880
#define NCHUNK (NN / 32)        // 64

__global__ __launch_bounds__(256, 1) void k_mma(int sel) {
    extern __shared__ char smem[];
    const uint32_t sb = smem_u32(smem);
    const int tid = threadIdx.x;
    const int lane = tid & 31;
    const int warp = tid >> 5;
    const int warpM = warp & 1;          // 2 warps in m
    const int warpN = warp >> 1;         // 4 warps in n
    const int m_off = warpM * 64;
    const int n_off = warpN * 32;

    const char* pAh = (const char*)g_Ah;
    const char* pAl = (const char*)g_Al;
    const char* pBh = sel ? (const char*)g_B1h : (const char*)g_B0h;
    const char* pBl = sel ? (const char*)g_B1l : (const char*)g_B0l;
    float* C = sel ? g_Y2 : g_Y1;

    const int m0 = blockIdx.x * 128;     // 16 m-tiles (fastest -> B reuse in L2)
    const int c0 = blockIdx.y * 128;     // 96 n-tiles

    auto load_stage = [&](int stg, int chunk) {
        const uint32_t base = sb + stg * STG;
        const int k0 = chunk * 32;
#pragma unroll
        for (int r = 0; r < 8; ++r) {
            int id = tid + r * 256;
            int mat = id >> 9;           // 0 Ah, 1 Al, 2 Bh, 3 Bl
            int rid = id & 511;
            int row = rid >> 2;
            int cc = rid & 3;            // 16B chunk within 64B row
            uint32_t so = base + mat * MATSZ + row * ROWB + cc * 16;
            size_t go;
            const char* p;
            if (mat < 2) {
                go = ((size_t)(m0 + row) * NN + k0 + cc * 8) * 2;
                p = mat ? pAl : pAh;
            } else {
                go = ((size_t)(c0 + row) * NN + k0 + cc * 8) * 2;
                p = (mat == 3) ? pBl : pBh;
            }
            cp16(so, p + go);
        }
    };

    float acc[4][4][4];
#pragma unroll
    for (int i = 0; i < 4; ++i)
#pragma unroll
        for (int j = 0; j < 4; ++j)
#pragma unroll
            for (int q = 0; q < 4; ++q) acc[i][j][q] = 0.f;

    load_stage(0, 0); CP_COMMIT();
    load_stage(1, 1); CP_COMMIT();

    const int grp = lane >> 3, lr = lane & 7;
    const int a_row_base = m_off + (grp & 1) * 8 + lr;     // + mf*16
    const int a_kc = grp >> 1;                              // chunk within k16
    const int b_row_base = n_off + lr;                      // + nf*8
    const int b_kc = grp & 1;

    for (int c = 0; c < NCHUNK; ++c) {
        const int st = c % NSTG;
        if (c + 1 < NCHUNK) CP_WAIT1(); else CP_WAIT0();
        __syncthreads();
        if (c + 2 < NCHUNK) { load_stage((c + 2) % NSTG, c + 2); CP_COMMIT(); }

        const uint32_t base = sb + st * STG;
#pragma unroll
        for (int ks = 0; ks < 2; ++ks) {
            const int kc0 = ks * 2;
            uint32_t ah[4][4], al[4][4], bh[4][2], bl[4][2];
#pragma unroll
            for (int mf = 0; mf < 4; ++mf) {
                uint32_t ad = base + (a_row_base + mf * 16) * ROWB + (a_kc + kc0) * 16;
                ldsm4(ah[mf], ad);
                ldsm4(al[mf], ad + MATSZ);
            }
#pragma unroll
            for (int nf = 0; nf < 4; ++nf) {
                uint32_t bd = base + 2 * MATSZ + (b_row_base + nf * 8) * ROWB + (b_kc + kc0) * 16;
                ldsm2(bh[nf], bd);
                ldsm2(bl[nf], bd + MATSZ);
            }
#pragma unroll
            for (int mf = 0; mf < 4; ++mf)
#pragma unroll
                for (int nf = 0; nf < 4; ++nf) mma16816(acc[mf][nf], ah[mf], bh[nf]);
#pragma unroll
            for (int mf = 0; mf < 4; ++mf)
#pragma unroll
                for (int nf = 0; nf < 4; ++nf) mma16816(acc[mf][nf], ah[mf], bl[nf]);
#pragma unroll
            for (int mf = 0; mf < 4; ++mf)
#pragma unroll
                for (int nf = 0; nf < 4; ++nf) mma16816(acc[mf][nf], al[mf], bh[nf]);
        }
        __syncthreads();
    }

    // epilogue: fp32 to C
#pragma unroll
    for (int mf = 0; mf < 4; ++mf) {
#pragma unroll
        for (int half = 0; half < 2; ++half) {
            int row = m0 + m_off + mf * 16 + half * 8 + (lane >> 2);
            float* cr = C + (size_t)row * BIS + c0 + n_off + (lane & 3) * 2;
#pragma unroll
            for (int nf = 0; nf < 4; ++nf) {
                float2 v = make_float2(acc[mf][nf][half * 2], acc[mf][nf][half * 2 + 1]);
                *(float2*)(cr + nf * 8) = v;
            }
        }
    }
}

// ---------------- 7. per-node generated weights + bias ----------------------
__global__ void k_weights(const float* __restrict__ E1, const float* __restrict__ E2,
                          const float* __restrict__ Wp, const float* __restrict__ Wp2,
                          const float* __restrict__ bp, const float* __restrict__ bp2) {
    int n = blockIdx.x, tid = threadIdx.x;
    __shared__ float e1[EE], e2[EE];
    if (tid < EE) e1[tid] = E1[n * EE + tid];
    else if (tid < 2 * EE) e2[tid - EE] = E2[n * EE + tid - EE];
    __syncthreads();
    float l1[EE], l2[EE];
#pragma unroll
    for (int d = 0; d < EE; ++d) { l1[d] = e1[d]; l2[d] = e2[d]; }
    for (int q = tid; q < PW; q += 256) {
        float acc = 0.f;
#pragma unroll
        for (int d = 0; d < EE; ++d)
            acc = fmaf(l1[d], Wp[d * PW + q], fmaf(l2[d], Wp2[d * PW + q], acc));
        g_W[(size_t)n * PW + q] = acc;
    }
    if (tid < OO) {
        float acc = 0.f;
#pragma unroll
        for (int d = 0; d < EE; ++d)
            acc = fmaf(l1[d], bp[d * OO + tid], fmaf(l2[d], bp2[d * OO + tid], acc));
        g_bias[n * OO + tid] = acc;
    }
}

// -------- 8. gconv ----------------------------------------------------------
__global__ __launch_bounds__(384) void k_gconv(float* __restrict__ out) {
    int n = blockIdx.x, tid = threadIdx.x;
    __shared__ float Ws[PW];
    __shared__ float bsh[OO];
    for (int q = tid; q < PW; q += 384) Ws[q] = g_W[(size_t)n * PW + q];
    if (tid < OO) bsh[tid] = g_bias[n * OO + tid];
    __syncthreads();
    int b = tid / SS, s = tid - b * SS;
    float acc[OO];
#pragma unroll
    for (int o = 0; o < OO; ++o) acc[o] = bsh[o];
    const float* Yb[3] = { g_Xt, g_Y1, g_Y2 };
#pragma unroll
    for (int k = 0; k < KK; ++k) {
        const float* yb = Yb[k] + (size_t)n * BIS + (size_t)b * II * SS + s;
        const float* wk = Ws + k * II * OO;
#pragma unroll 4
        for (int i = 0; i < II; ++i) {
            float v = yb[i * SS];
            const float* wr = wk + i * OO;
#pragma unroll
            for (int o = 0; o < OO; ++o) acc[o] = fmaf(v, wr[o], acc[o]);
        }
    }
#pragma unroll
    for (int o = 0; o < OO; ++o)
        out[(((size_t)b * OO + o) * NN + n) * SS + s] = acc[o];
}

// ---------------------------------------------------------------------------
extern "C" void kernel_launch(void* const* d_in, const int* in_sizes, int n_in,
                              void* d_out, int out_size) {
    const float* x    = (const float*)d_in[0];
    const float* E1   = (const float*)d_in[1];
    const float* E2   = (const float*)d_in[2];
    const float* Wp   = (const float*)d_in[3];
    const float* Wp2  = (const float*)d_in[4];
    const float* bp   = (const float*)d_in[5];
    const float* bp2  = (const float*)d_in[6];
    const float* fc0w = (const float*)d_in[7];
    const float* fc0b = (const float*)d_in[8];
    const float* fc1w = (const float*)d_in[9];
    const float* fc1b = (const float*)d_in[10];
    const float* fc2w = (const float*)d_in[11];
    const float* fc2b = (const float*)d_in[12];
    float* out = (float*)d_out;

    cudaFuncSetAttribute(k_mma, cudaFuncAttributeMaxDynamicSharedMemorySize, SMTOT);

    k_h1<<<II * NN / 256, 256>>>(x, fc0w, fc0b);
    k_h2<<<II * EE, 256>>>(fc1w, fc1b);
    k_m<<<1, 256>>>(fc2w, fc2b);
    k_adj<<<NN, 256>>>(E1, E2);
    k_transpose<<<NN * 1024 / 256, 256>>>(x);

    dim3 gt(BIS / 32, NN / 32);
    k_splitT<<<gt, 256>>>(0);                     // X^T  -> B0h/B0l

    dim3 gg(NN / 128, BIS / 128);
    k_mma<<<gg, 256, SMTOT>>>(0);                 // Y1 = S @ X
    k_splitT<<<gt, 256>>>(1);                     // Y1^T -> B1h/B1l
    k_mma<<<gg, 256, SMTOT>>>(1);                 // Y2 = S @ Y1

    k_weights<<<NN, 256>>>(E1, E2, Wp, Wp2, bp, bp2);
    k_gconv<<<NN, 384>>>(out);
}

// round 7
// speedup vs baseline: 2.7785x; 1.3539x over previous
#include <cuda_runtime.h>
#include <cuda_fp16.h>
#include <cstdint>

#define NN   2048
#define BB   32
#define II   32
#define OO   32
#define SS   12
#define EE   16
#define KK   3          // K+1 hops
#define BIS  12288      // B*II*SS
#define PW   (KK*II*OO)

// ---------------- scratch (device globals) ----------------------------------
__device__ float g_h1[II * NN];
__device__ float g_h2[II * EE];
__device__ float g_m[EE * EE];
__device__ float g_Xt[(size_t)NN * BIS];
__device__ float g_Y1[(size_t)NN * BIS];
__device__ float g_Y2[(size_t)NN * BIS];
__device__ float g_W[(size_t)NN * PW];
__device__ float g_bias[NN * OO];
// fp16 operands (A: hi only -- 2-term split; B: hi+lo)
__device__ __align__(16) __half g_Ah[(size_t)NN * NN];
__device__ __align__(16) __half g_B0h[(size_t)BIS * NN];
__device__ __align__(16) __half g_B0l[(size_t)BIS * NN];
__device__ __align__(16) __half g_B1h[(size_t)BIS * NN];
__device__ __align__(16) __half g_B1l[(size_t)BIS * NN];

// ---------------- helpers ----------------------------------------------------
__device__ __forceinline__ uint32_t smem_u32(const void* p) {
    uint32_t a;
    asm("{ .reg .u64 t; cvta.to.shared.u64 t, %1; cvt.u32.u64 %0, t; }" : "=r"(a) : "l"(p));
    return a;
}
__device__ __forceinline__ void cp16(uint32_t dst, const void* src) {
    asm volatile("cp.async.cg.shared.global [%0], [%1], 16;" :: "r"(dst), "l"(src) : "memory");
}
#define CP_COMMIT() asm volatile("cp.async.commit_group;" ::: "memory")
#define CP_WAIT2()  asm volatile("cp.async.wait_group 2;" ::: "memory")
#define CP_WAIT0()  asm volatile("cp.async.wait_group 0;" ::: "memory")

__device__ __forceinline__ void ldsm4(uint32_t* r, uint32_t addr) {
    asm volatile("ldmatrix.sync.aligned.m8n8.x4.shared.b16 {%0,%1,%2,%3}, [%4];"
                 : "=r"(r[0]), "=r"(r[1]), "=r"(r[2]), "=r"(r[3]) : "r"(addr));
}
__device__ __forceinline__ void ldsm2(uint32_t* r, uint32_t addr) {
    asm volatile("ldmatrix.sync.aligned.m8n8.x2.shared.b16 {%0,%1}, [%2];"
                 : "=r"(r[0]), "=r"(r[1]) : "r"(addr));
}
__device__ __forceinline__ void mma16816(float* c, const uint32_t* a, const uint32_t* b) {
    asm volatile(
        "mma.sync.aligned.m16n8k16.row.col.f32.f16.f16.f32 "
        "{%0,%1,%2,%3}, {%4,%5,%6,%7}, {%8,%9}, {%0,%1,%2,%3};"
        : "+f"(c[0]), "+f"(c[1]), "+f"(c[2]), "+f"(c[3])
        : "r"(a[0]), "r"(a[1]), "r"(a[2]), "r"(a[3]), "r"(b[0]), "r"(b[1]));
}

// ---------------- 1. h1 -----------------------------------------------------
__global__ void k_h1(const float* __restrict__ x,
                     const float* __restrict__ fc0w,
                     const float* __restrict__ fc0b) {
    int idx = blockIdx.x * 256 + threadIdx.x;
    float acc = fc0b[0];
    const float* xr = x + (size_t)idx * SS;
#pragma unroll
    for (int s = 0; s < SS; ++s) acc = fmaf(xr[s], fc0w[s], acc);
    g_h1[idx] = tanhf(acc);
}

// ---------------- 2. h2 -----------------------------------------------------
__global__ void k_h2(const float* __restrict__ fc1w,
                     const float* __restrict__ fc1b) {
    int i = blockIdx.x >> 4;
    int d = blockIdx.x & 15;
    int tid = threadIdx.x;
    float p = 0.f;
    for (int n = tid; n < NN; n += 256)
        p = fmaf(g_h1[i * NN + n], fc1w[d * NN + n], p);
    __shared__ float red[256];
    red[tid] = p; __syncthreads();
    for (int st = 128; st > 0; st >>= 1) {
        if (tid < st) red[tid] += red[tid + st];
        __syncthreads();
    }
    if (tid == 0) g_h2[i * EE + d] = tanhf(red[0] + fc1b[d]);
}

// ---------------- 3. m ------------------------------------------------------
__global__ void k_m(const float* __restrict__ fc2w,
                    const float* __restrict__ fc2b) {
    int t = threadIdx.x;
    int d = t >> 4, e = t & 15;
    float acc = fc2b[e];
#pragma unroll
    for (int i = 0; i < II; ++i) acc = fmaf(g_h2[i * EE + d], fc2w[e * II + i], acc);
    g_m[d * EE + e] = tanhf(acc);
}

// ------- 4. adjacency softmax -> fp16 (warp-per-row, no block barriers) -----
__global__ __launch_bounds__(128) void k_adj(const float* __restrict__ E1,
                                             const float* __restrict__ E2) {
    __shared__ float buf[4][NN];          // 32 KB
    int w = threadIdx.x >> 5, lane = threadIdx.x & 31;
    int n = blockIdx.x * 4 + w;

    // p[e] on lanes 0..15, then broadcast
    float pv = 0.f;
    if (lane < EE) {
#pragma unroll
        for (int d = 0; d < EE; ++d) pv = fmaf(E1[n * EE + d], g_m[d * EE + lane], pv);
    }
    float pl[EE];
#pragma unroll
    for (int e = 0; e < EE; ++e) pl[e] = __shfl_sync(0xffffffffu, pv, e);

    float lmax = 0.f;   // relu => logits >= 0
    for (int mc = lane; mc < NN; mc += 32) {
        const float4* er = (const float4*)(E2 + mc * EE);
        float4 q0 = er[0], q1 = er[1], q2 = er[2], q3 = er[3];
        float a = 0.f;
        a = fmaf(pl[0], q0.x, a);  a = fmaf(pl[1], q0.y, a);
        a = fmaf(pl[2], q0.z, a);  a = fmaf(pl[3], q0.w, a);
        a = fmaf(pl[4], q1.x, a);  a = fmaf(pl[5], q1.y, a);
        a = fmaf(pl[6], q1.z, a);  a = fmaf(pl[7], q1.w, a);
        a = fmaf(pl[8], q2.x, a);  a = fmaf(pl[9], q2.y, a);
        a = fmaf(pl[10], q2.z, a); a = fmaf(pl[11], q2.w, a);
        a = fmaf(pl[12], q3.x, a); a = fmaf(pl[13], q3.y, a);
        a = fmaf(pl[14], q3.z, a); a = fmaf(pl[15], q3.w, a);
        a = fmaxf(a, 0.f);
        buf[w][mc] = a;
        lmax = fmaxf(lmax, a);
    }
#pragma unroll
    for (int o = 16; o; o >>= 1) lmax = fmaxf(lmax, __shfl_xor_sync(0xffffffffu, lmax, o));

    float lsum = 0.f;
    for (int mc = lane; mc < NN; mc += 32) {
        float v = __expf(buf[w][mc] - lmax);
        buf[w][mc] = v;
        lsum += v;
    }
#pragma unroll
    for (int o = 16; o; o >>= 1) lsum += __shfl_xor_sync(0xffffffffu, lsum, o);
    float inv = 1.0f / lsum;

    for (int mc = lane; mc < NN; mc += 32)
        g_Ah[(size_t)n * NN + mc] = __float2half_rn(buf[w][mc] * inv);
}

// ---------------- 5. Xt transpose -------------------------------------------
__global__ void k_transpose(const float* __restrict__ x) {
    int idx = blockIdx.x * 256 + threadIdx.x;
    int m  = idx >> 10;
    int bi = idx & 1023;
    const float* src = x + ((size_t)bi * NN + m) * SS;
    float* dst = g_Xt + (size_t)m * BIS + bi * SS;
#pragma unroll
    for (int s = 0; s < SS; ++s) dst[s] = src[s];
}

// --------- 5b. transpose+split: [2048,12288]f32 -> [12288,2048] fp16 h/l ----
__global__ __launch_bounds__(256) void k_splitT(int which) {
    const float* __restrict__ src = which ? g_Y1 : g_Xt;
    __half* __restrict__ dh = which ? g_B1h : g_B0h;
    __half* __restrict__ dl = which ? g_B1l : g_B0l;
    __shared__ float t[32][33];
    int tx = threadIdx.x & 31, ty = threadIdx.x >> 5;
    int c0 = blockIdx.x * 32;
    int k0 = blockIdx.y * 32;
#pragma unroll
    for (int j = 0; j < 32; j += 8)
        t[ty + j][tx] = src[(size_t)(k0 + ty + j) * BIS + c0 + tx];
    __syncthreads();
#pragma unroll
    for (int j = 0; j < 32; j += 8) {
        float v = t[tx][ty + j];
        __half h = __float2half_rn(v);
        __half l = __float2half_rn(v - __half2float(h));
        size_t o = (size_t)(c0 + ty + j) * NN + k0 + tx;
        dh[o] = h;
        dl[o] = l;
    }
}

// ============== 6. mma.sync GEMM  C[2048,12288] = S @ X =====================
// 2-term fp16: C = Ah*Bh + Ah*Bl.  BM=128,BN=128,BK=32, 4-stage cp.async.
#define ROWB 80
#define MATSZ (128 * ROWB)      // 10240 B per matrix tile
#define STG   (3 * MATSZ)       // Ah, Bh, Bl  = 30720
#define NSTG  4
#define SMTOT (NSTG * STG)      // 122880
#define NCHUNK (NN / 32)        // 64

__global__ __launch_bounds__(256, 1) void k_mma(int sel) {
    extern __shared__ char smem[];
    const uint32_t sb = smem_u32(smem);
    const int tid = threadIdx.x;
    const int lane = tid & 31;
    const int warp = tid >> 5;
    const int m_off = (warp & 1) * 64;   // 2 warps in m
    const int n_off = (warp >> 1) * 32;  // 4 warps in n

    const char* pAh = (const char*)g_Ah;
    const char* pBh = sel ? (const char*)g_B1h : (const char*)g_B0h;
    const char* pBl = sel ? (const char*)g_B1l : (const char*)g_B0l;
    float* C = sel ? g_Y2 : g_Y1;

    const int m0 = blockIdx.x * 128;     // m fastest -> B reuse in L2
    const int c0 = blockIdx.y * 128;

    auto load_stage = [&](int stg, int chunk) {
        const uint32_t base = sb + stg * STG;
        const int k0 = chunk * 32;
#pragma unroll
        for (int r = 0; r < 6; ++r) {
            int id = tid + r * 256;      // 0..1535
            int mat = id >> 9;           // 0 Ah, 1 Bh, 2 Bl
            int rid = id & 511;
            int row = rid >> 2;
            int cc = rid & 3;
            uint32_t so = base + mat * MATSZ + row * ROWB + cc * 16;
            size_t go;
            const char* p;
            if (mat == 0) { go = ((size_t)(m0 + row) * NN + k0 + cc * 8) * 2; p = pAh; }
            else          { go = ((size_t)(c0 + row) * NN + k0 + cc * 8) * 2; p = (mat == 2) ? pBl : pBh; }
            cp16(so, p + go);
        }
    };

    float acc[4][4][4];
#pragma unroll
    for (int i = 0; i < 4; ++i)
#pragma unroll
        for (int j = 0; j < 4; ++j)
#pragma unroll
            for (int q = 0; q < 4; ++q) acc[i][j][q] = 0.f;

    load_stage(0, 0); CP_COMMIT();
    load_stage(1, 1); CP_COMMIT();
    load_stage(2, 2); CP_COMMIT();

    const int grp = lane >> 3, lr = lane & 7;
    const int a_row_base = m_off + (grp & 1) * 8 + lr;     // + mf*16
    const int a_kc = grp >> 1;
    const int b_row_base = n_off + lr;                      // + nf*8
    const int b_kc = grp & 1;

    for (int c = 0; c < NCHUNK; ++c) {
        const int st = c & 3;
        if (c + 1 < NCHUNK) CP_WAIT2(); else CP_WAIT0();
        __syncthreads();                 // stage c ready; compute c-1 done everywhere
        if (c + 3 < NCHUNK) load_stage((c + 3) & 3, c + 3);
        CP_COMMIT();

        const uint32_t base = sb + st * STG;
#pragma unroll
        for (int ks = 0; ks < 2; ++ks) {
            const int kc0 = ks * 2;
            uint32_t ah[4][4], bh[4][2], bl[4][2];
#pragma unroll
            for (int mf = 0; mf < 4; ++mf) {
                uint32_t ad = base + (a_row_base + mf * 16) * ROWB + (a_kc + kc0) * 16;
                ldsm4(ah[mf], ad);
            }
#pragma unroll
            for (int nf = 0; nf < 4; ++nf) {
                uint32_t bd = base + MATSZ + (b_row_base + nf * 8) * ROWB + (b_kc + kc0) * 16;
                ldsm2(bh[nf], bd);
                ldsm2(bl[nf], bd + MATSZ);
            }
#pragma unroll
            for (int mf = 0; mf < 4; ++mf)
#pragma unroll
                for (int nf = 0; nf < 4; ++nf) mma16816(acc[mf][nf], ah[mf], bh[nf]);
#pragma unroll
            for (int mf = 0; mf < 4; ++mf)
#pragma unroll
                for (int nf = 0; nf < 4; ++nf) mma16816(acc[mf][nf], ah[mf], bl[nf]);
        }
    }

    // epilogue: fp32 to C
#pragma unroll
    for (int mf = 0; mf < 4; ++mf) {
#pragma unroll
        for (int half = 0; half < 2; ++half) {
            int row = m0 + m_off + mf * 16 + half * 8 + (lane >> 2);
            float* cr = C + (size_t)row * BIS + c0 + n_off + (lane & 3) * 2;
#pragma unroll
            for (int nf = 0; nf < 4; ++nf) {
                float2 v = make_float2(acc[mf][nf][half * 2], acc[mf][nf][half * 2 + 1]);
                *(float2*)(cr + nf * 8) = v;
            }
        }
    }
}

// ---------------- 7. per-node generated weights + bias ----------------------
__global__ void k_weights(const float* __restrict__ E1, const float* __restrict__ E2,
                          const float* __restrict__ Wp, const float* __restrict__ Wp2,
                          const float* __restrict__ bp, const float* __restrict__ bp2) {
    int n = blockIdx.x, tid = threadIdx.x;
    __shared__ float e1[EE], e2[EE];
    if (tid < EE) e1[tid] = E1[n * EE + tid];
    else if (tid < 2 * EE) e2[tid - EE] = E2[n * EE + tid - EE];
    __syncthreads();
    float l1[EE], l2[EE];
#pragma unroll
    for (int d = 0; d < EE; ++d) { l1[d] = e1[d]; l2[d] = e2[d]; }
    for (int q = tid; q < PW; q += 256) {
        float acc = 0.f;
#pragma unroll
        for (int d = 0; d < EE; ++d)
            acc = fmaf(l1[d], Wp[d * PW + q], fmaf(l2[d], Wp2[d * PW + q], acc));
        g_W[(size_t)n * PW + q] = acc;
    }
    if (tid < OO) {
        float acc = 0.f;
#pragma unroll
        for (int d = 0; d < EE; ++d)
            acc = fmaf(l1[d], bp[d * OO + tid], fmaf(l2[d], bp2[d * OO + tid], acc));
        g_bias[n * OO + tid] = acc;
    }
}

// -------- 8. gconv ----------------------------------------------------------
__global__ __launch_bounds__(384) void k_gconv(float* __restrict__ out) {
    int n = blockIdx.x, tid = threadIdx.x;
    __shared__ float Ws[PW];
    __shared__ float bsh[OO];
    for (int q = tid; q < PW; q += 384) Ws[q] = g_W[(size_t)n * PW + q];
    if (tid < OO) bsh[tid] = g_bias[n * OO + tid];
    __syncthreads();
    int b = tid / SS, s = tid - b * SS;
    float acc[OO];
#pragma unroll
    for (int o = 0; o < OO; ++o) acc[o] = bsh[o];
    const float* Yb[3] = { g_Xt, g_Y1, g_Y2 };
#pragma unroll
    for (int k = 0; k < KK; ++k) {
        const float* yb = Yb[k] + (size_t)n * BIS + (size_t)b * II * SS + s;
        const float* wk = Ws + k * II * OO;
#pragma unroll 4
        for (int i = 0; i < II; ++i) {
            float v = yb[i * SS];
            const float* wr = wk + i * OO;
#pragma unroll
            for (int o = 0; o < OO; ++o) acc[o] = fmaf(v, wr[o], acc[o]);
        }
    }
#pragma unroll
    for (int o = 0; o < OO; ++o)
        out[(((size_t)b * OO + o) * NN + n) * SS + s] = acc[o];
}

// ---------------------------------------------------------------------------
extern "C" void kernel_launch(void* const* d_in, const int* in_sizes, int n_in,
                              void* d_out, int out_size) {
    const float* x    = (const float*)d_in[0];
    const float* E1   = (const float*)d_in[1];
    const float* E2   = (const float*)d_in[2];
    const float* Wp   = (const float*)d_in[3];
    const float* Wp2  = (const float*)d_in[4];
    const float* bp   = (const float*)d_in[5];
    const float* bp2  = (const float*)d_in[6];
    const float* fc0w = (const float*)d_in[7];
    const float* fc0b = (const float*)d_in[8];
    const float* fc1w = (const float*)d_in[9];
    const float* fc1b = (const float*)d_in[10];
    const float* fc2w = (const float*)d_in[11];
    const float* fc2b = (const float*)d_in[12];
    float* out = (float*)d_out;

    cudaFuncSetAttribute(k_mma, cudaFuncAttributeMaxDynamicSharedMemorySize, SMTOT);

    k_h1<<<II * NN / 256, 256>>>(x, fc0w, fc0b);
    k_h2<<<II * EE, 256>>>(fc1w, fc1b);
    k_m<<<1, 256>>>(fc2w, fc2b);
    k_adj<<<NN / 4, 128>>>(E1, E2);
    k_transpose<<<NN * 1024 / 256, 256>>>(x);

    dim3 gt(BIS / 32, NN / 32);
    k_splitT<<<gt, 256>>>(0);                     // X^T  -> B0h/B0l

    dim3 gg(NN / 128, BIS / 128);
    k_mma<<<gg, 256, SMTOT>>>(0);                 // Y1 = S @ X
    k_splitT<<<gt, 256>>>(1);                     // Y1^T -> B1h/B1l
    k_mma<<<gg, 256, SMTOT>>>(1);                 // Y2 = S @ Y1

    k_weights<<<NN, 256>>>(E1, E2, Wp, Wp2, bp, bp2);
    k_gconv<<<NN, 384>>>(out);
}

// round 10
// speedup vs baseline: 3.4168x; 1.2298x over previous
#include <cuda_runtime.h>
#include <cuda_fp16.h>
#include <cstdint>

#define NN   2048
#define BB   32
#define II   32
#define OO   32
#define SS   12
#define EE   16
#define KK   3          // K+1 hops
#define BIS  12288      // B*II*SS
#define PW   (KK*II*OO)

// ---------------- scratch (device globals) ----------------------------------
__device__ float g_h1[II * NN];
__device__ float g_h2[II * EE];
__device__ float g_m[EE * EE];
__device__ float g_Y1[(size_t)NN * BIS];
__device__ float g_Y2[(size_t)NN * BIS];
__device__ float g_W[(size_t)NN * PW];
__device__ float g_bias[NN * OO];
// fp16 operands
__device__ __align__(16) __half g_Ah[(size_t)NN * NN];
__device__ __align__(16) __half g_B0h[(size_t)BIS * NN];
__device__ __align__(16) __half g_B0l[(size_t)BIS * NN];
__device__ __align__(16) __half g_B1h[(size_t)BIS * NN];

// ---------------- helpers ----------------------------------------------------
__device__ __forceinline__ uint32_t smem_u32(const void* p) {
    uint32_t a;
    asm("{ .reg .u64 t; cvta.to.shared.u64 t, %1; cvt.u32.u64 %0, t; }" : "=r"(a) : "l"(p));
    return a;
}
__device__ __forceinline__ void cp16(uint32_t dst, const void* src) {
    asm volatile("cp.async.cg.shared.global [%0], [%1], 16;" :: "r"(dst), "l"(src) : "memory");
}
#define CP_COMMIT() asm volatile("cp.async.commit_group;" ::: "memory")
#define CP_WAIT2()  asm volatile("cp.async.wait_group 2;" ::: "memory")
#define CP_WAIT0()  asm volatile("cp.async.wait_group 0;" ::: "memory")

__device__ __forceinline__ void ldsm4(uint32_t* r, uint32_t addr) {
    asm volatile("ldmatrix.sync.aligned.m8n8.x4.shared.b16 {%0,%1,%2,%3}, [%4];"
                 : "=r"(r[0]), "=r"(r[1]), "=r"(r[2]), "=r"(r[3]) : "r"(addr));
}
__device__ __forceinline__ void ldsm2(uint32_t* r, uint32_t addr) {
    asm volatile("ldmatrix.sync.aligned.m8n8.x2.shared.b16 {%0,%1}, [%2];"
                 : "=r"(r[0]), "=r"(r[1]) : "r"(addr));
}
__device__ __forceinline__ void mma16816(float* c, const uint32_t* a, const uint32_t* b) {
    asm volatile(
        "mma.sync.aligned.m16n8k16.row.col.f32.f16.f16.f32 "
        "{%0,%1,%2,%3}, {%4,%5,%6,%7}, {%8,%9}, {%0,%1,%2,%3};"
        : "+f"(c[0]), "+f"(c[1]), "+f"(c[2]), "+f"(c[3])
        : "r"(a[0]), "r"(a[1]), "r"(a[2]), "r"(a[3]), "r"(b[0]), "r"(b[1]));
}

// ---------------- 1. h1 -----------------------------------------------------
__global__ void k_h1(const float* __restrict__ x,
                     const float* __restrict__ fc0w,
                     const float* __restrict__ fc0b) {
    int idx = blockIdx.x * 256 + threadIdx.x;
    float acc = fc0b[0];
    const float* xr = x + (size_t)idx * SS;
#pragma unroll
    for (int s = 0; s < SS; ++s) acc = fmaf(xr[s], fc0w[s], acc);
    g_h1[idx] = tanhf(acc);
}

// ---------------- 2. h2 -----------------------------------------------------
__global__ void k_h2(const float* __restrict__ fc1w,
                     const float* __restrict__ fc1b) {
    int i = blockIdx.x >> 4;
    int d = blockIdx.x & 15;
    int tid = threadIdx.x;
    float p = 0.f;
    for (int n = tid; n < NN; n += 256)
        p = fmaf(g_h1[i * NN + n], fc1w[d * NN + n], p);
    __shared__ float red[256];
    red[tid] = p; __syncthreads();
    for (int st = 128; st > 0; st >>= 1) {
        if (tid < st) red[tid] += red[tid + st];
        __syncthreads();
    }
    if (tid == 0) g_h2[i * EE + d] = tanhf(red[0] + fc1b[d]);
}

// ---------------- 3. m ------------------------------------------------------
__global__ void k_m(const float* __restrict__ fc2w,
                    const float* __restrict__ fc2b) {
    int t = threadIdx.x;
    int d = t >> 4, e = t & 15;
    float acc = fc2b[e];
#pragma unroll
    for (int i = 0; i < II; ++i) acc = fmaf(g_h2[i * EE + d], fc2w[e * II + i], acc);
    g_m[d * EE + e] = tanhf(acc);
}

// ------- 4. adjacency softmax -> fp16 (warp-per-row) ------------------------
__global__ __launch_bounds__(128) void k_adj(const float* __restrict__ E1,
                                             const float* __restrict__ E2) {
    __shared__ float buf[4][NN];
    int w = threadIdx.x >> 5, lane = threadIdx.x & 31;
    int n = blockIdx.x * 4 + w;

    float pv = 0.f;
    if (lane < EE) {
#pragma unroll
        for (int d = 0; d < EE; ++d) pv = fmaf(E1[n * EE + d], g_m[d * EE + lane], pv);
    }
    float pl[EE];
#pragma unroll
    for (int e = 0; e < EE; ++e) pl[e] = __shfl_sync(0xffffffffu, pv, e);

    float lmax = 0.f;   // relu => logits >= 0
    for (int mc = lane; mc < NN; mc += 32) {
        const float4* er = (const float4*)(E2 + mc * EE);
        float4 q0 = er[0], q1 = er[1], q2 = er[2], q3 = er[3];
        float a = 0.f;
        a = fmaf(pl[0], q0.x, a);  a = fmaf(pl[1], q0.y, a);
        a = fmaf(pl[2], q0.z, a);  a = fmaf(pl[3], q0.w, a);
        a = fmaf(pl[4], q1.x, a);  a = fmaf(pl[5], q1.y, a);
        a = fmaf(pl[6], q1.z, a);  a = fmaf(pl[7], q1.w, a);
        a = fmaf(pl[8], q2.x, a);  a = fmaf(pl[9], q2.y, a);
        a = fmaf(pl[10], q2.z, a); a = fmaf(pl[11], q2.w, a);
        a = fmaf(pl[12], q3.x, a); a = fmaf(pl[13], q3.y, a);
        a = fmaf(pl[14], q3.z, a); a = fmaf(pl[15], q3.w, a);
        a = fmaxf(a, 0.f);
        buf[w][mc] = a;
        lmax = fmaxf(lmax, a);
    }
#pragma unroll
    for (int o = 16; o; o >>= 1) lmax = fmaxf(lmax, __shfl_xor_sync(0xffffffffu, lmax, o));

    float lsum = 0.f;
    for (int mc = lane; mc < NN; mc += 32) {
        float v = __expf(buf[w][mc] - lmax);
        buf[w][mc] = v;
        lsum += v;
    }
#pragma unroll
    for (int o = 16; o; o >>= 1) lsum += __shfl_xor_sync(0xffffffffu, lsum, o);
    float inv = 1.0f / lsum;

    for (int mc = lane; mc < NN; mc += 32)
        g_Ah[(size_t)n * NN + mc] = __float2half_rn(buf[w][mc] * inv);
}

// --------- 5a. B0 split directly from x: B0[(b,i,s)][m] = x[b,i,m,s] --------
__global__ __launch_bounds__(256) void k_split0(const float* __restrict__ x) {
    int bi = blockIdx.x;
    int m = blockIdx.y * 256 + threadIdx.x;
    const float* src = x + ((size_t)bi * NN + m) * SS;
    float v[SS];
#pragma unroll
    for (int s = 0; s < SS; ++s) v[s] = src[s];
#pragma unroll
    for (int s = 0; s < SS; ++s) {
        __half h = __float2half_rn(v[s]);
        __half l = __float2half_rn(v[s] - __half2float(h));
        size_t o = (size_t)(bi * SS + s) * NN + m;
        g_B0h[o] = h;
        g_B0l[o] = l;
    }
}

// --------- 5b. B1h = fp16( Y1^T ) -------------------------------------------
__global__ __launch_bounds__(256) void k_split1() {
    __shared__ float t[32][33];
    int tx = threadIdx.x & 31, ty = threadIdx.x >> 5;
    int c0 = blockIdx.x * 32;
    int k0 = blockIdx.y * 32;
#pragma unroll
    for (int j = 0; j < 32; j += 8)
        t[ty + j][tx] = g_Y1[(size_t)(k0 + ty + j) * BIS + c0 + tx];
    __syncthreads();
#pragma unroll
    for (int j = 0; j < 32; j += 8) {
        float v = t[tx][ty + j];
        g_B1h[(size_t)(c0 + ty + j) * NN + k0 + tx] = __float2half_rn(v);
    }
}

// ============== 6a. GEMM1  Y1 = S @ X   (2-term: Ah*Bh + Ah*Bl) =============
#define ROWB 80
#define MATSZ (128 * ROWB)
#define STG   (3 * MATSZ)
#define NSTG  4
#define SMTOT (NSTG * STG)
#define NCHUNK (NN / 32)

__global__ __launch_bounds__(256, 1) void k_mma1() {
    extern __shared__ char smem[];
    const uint32_t sb = smem_u32(smem);
    const int tid = threadIdx.x;
    const int lane = tid & 31;
    const int warp = tid >> 5;
    const int m_off = (warp & 1) * 64;
    const int n_off = (warp >> 1) * 32;

    const char* pAh = (const char*)g_Ah;
    const char* pBh = (const char*)g_B0h;
    const char* pBl = (const char*)g_B0l;
    float* C = g_Y1;

    const int m0 = blockIdx.x * 128;
    const int c0 = blockIdx.y * 128;

    auto load_stage = [&](int stg, int chunk) {
        const uint32_t base = sb + stg * STG;
        const int k0 = chunk * 32;
#pragma unroll
        for (int r = 0; r < 6; ++r) {
            int id = tid + r * 256;
            int mat = id >> 9;
            int rid = id & 511;
            int row = rid >> 2;
            int cc = rid & 3;
            uint32_t so = base + mat * MATSZ + row * ROWB + cc * 16;
            size_t go;
            const char* p;
            if (mat == 0) { go = ((size_t)(m0 + row) * NN + k0 + cc * 8) * 2; p = pAh; }
            else          { go = ((size_t)(c0 + row) * NN + k0 + cc * 8) * 2; p = (mat == 2) ? pBl : pBh; }
            cp16(so, p + go);
        }
    };

    float acc[4][4][4];
#pragma unroll
    for (int i = 0; i < 4; ++i)
#pragma unroll
        for (int j = 0; j < 4; ++j)
#pragma unroll
            for (int q = 0; q < 4; ++q) acc[i][j][q] = 0.f;

    load_stage(0, 0); CP_COMMIT();
    load_stage(1, 1); CP_COMMIT();
    load_stage(2, 2); CP_COMMIT();

    const int grp = lane >> 3, lr = lane & 7;
    const int a_row_base = m_off + (grp & 1) * 8 + lr;
    const int a_kc = grp >> 1;
    const int b_row_base = n_off + lr;
    const int b_kc = grp & 1;

    for (int c = 0; c < NCHUNK; ++c) {
        const int st = c & 3;
        if (c + 1 < NCHUNK) CP_WAIT2(); else CP_WAIT0();
        __syncthreads();
        if (c + 3 < NCHUNK) load_stage((c + 3) & 3, c + 3);
        CP_COMMIT();

        const uint32_t base = sb + st * STG;
#pragma unroll
        for (int ks = 0; ks < 2; ++ks) {
            const int kc0 = ks * 2;
            uint32_t ah[4][4], bh[4][2], bl[4][2];
#pragma unroll
            for (int mf = 0; mf < 4; ++mf) {
                uint32_t ad = base + (a_row_base + mf * 16) * ROWB + (a_kc + kc0) * 16;
                ldsm4(ah[mf], ad);
            }
#pragma unroll
            for (int nf = 0; nf < 4; ++nf) {
                uint32_t bd = base + MATSZ + (b_row_base + nf * 8) * ROWB + (b_kc + kc0) * 16;
                ldsm2(bh[nf], bd);
                ldsm2(bl[nf], bd + MATSZ);
            }
#pragma unroll
            for (int mf = 0; mf < 4; ++mf)
#pragma unroll
                for (int nf = 0; nf < 4; ++nf) mma16816(acc[mf][nf], ah[mf], bh[nf]);
#pragma unroll
            for (int mf = 0; mf < 4; ++mf)
#pragma unroll
                for (int nf = 0; nf < 4; ++nf) mma16816(acc[mf][nf], ah[mf], bl[nf]);
        }
    }

#pragma unroll
    for (int mf = 0; mf < 4; ++mf) {
#pragma unroll
        for (int half = 0; half < 2; ++half) {
            int row = m0 + m_off + mf * 16 + half * 8 + (lane >> 2);
            float* cr = C + (size_t)row * BIS + c0 + n_off + (lane & 3) * 2;
#pragma unroll
            for (int nf = 0; nf < 4; ++nf) {
                float2 v = make_float2(acc[mf][nf][half * 2], acc[mf][nf][half * 2 + 1]);
                *(float2*)(cr + nf * 8) = v;
            }
        }
    }
}

// ============== 6b. GEMM2  Y2 = S @ Y1  (1-term: Ah*Bh) =====================
#define STG2  (2 * MATSZ)
#define NSTG2 4
#define SMTOT2 (NSTG2 * STG2)

__global__ __launch_bounds__(256, 1) void k_mma2() {
    extern __shared__ char smem[];
    const uint32_t sb = smem_u32(smem);
    const int tid = threadIdx.x;
    const int lane = tid & 31;
    const int warp = tid >> 5;
    const int m_off = (warp & 1) * 64;
    const int n_off = (warp >> 1) * 32;

    const char* pAh = (const char*)g_Ah;
    const char* pBh = (const char*)g_B1h;
    float* C = g_Y2;

    const int m0 = blockIdx.x * 128;
    const int c0 = blockIdx.y * 128;

    auto load_stage = [&](int stg, int chunk) {
        const uint32_t base = sb + stg * STG2;
        const int k0 = chunk * 32;
#pragma unroll
        for (int r = 0; r < 4; ++r) {
            int id = tid + r * 256;
            int mat = id >> 9;
            int rid = id & 511;
            int row = rid >> 2;
            int cc = rid & 3;
            uint32_t so = base + mat * MATSZ + row * ROWB + cc * 16;
            size_t go;
            const char* p;
            if (mat == 0) { go = ((size_t)(m0 + row) * NN + k0 + cc * 8) * 2; p = pAh; }
            else          { go = ((size_t)(c0 + row) * NN + k0 + cc * 8) * 2; p = pBh; }
            cp16(so, p + go);
        }
    };

    float acc[4][4][4];
#pragma unroll
    for (int i = 0; i < 4; ++i)
#pragma unroll
        for (int j = 0; j < 4; ++j)
#pragma unroll
            for (int q = 0; q < 4; ++q) acc[i][j][q] = 0.f;

    load_stage(0, 0); CP_COMMIT();
    load_stage(1, 1); CP_COMMIT();
    load_stage(2, 2); CP_COMMIT();

    const int grp = lane >> 3, lr = lane & 7;
    const int a_row_base = m_off + (grp & 1) * 8 + lr;
    const int a_kc = grp >> 1;
    const int b_row_base = n_off + lr;
    const int b_kc = grp & 1;

    for (int c = 0; c < NCHUNK; ++c) {
        const int st = c & 3;
        if (c + 1 < NCHUNK) CP_WAIT2(); else CP_WAIT0();
        __syncthreads();
        if (c + 3 < NCHUNK) load_stage((c + 3) & 3, c + 3);
        CP_COMMIT();

        const uint32_t base = sb + st * STG2;
#pragma unroll
        for (int ks = 0; ks < 2; ++ks) {
            const int kc0 = ks * 2;
            uint32_t ah[4][4], bh[4][2];
#pragma unroll
            for (int mf = 0; mf < 4; ++mf) {
                uint32_t ad = base + (a_row_base + mf * 16) * ROWB + (a_kc + kc0) * 16;
                ldsm4(ah[mf], ad);
            }
#pragma unroll
            for (int nf = 0; nf < 4; ++nf) {
                uint32_t bd = base + MATSZ + (b_row_base + nf * 8) * ROWB + (b_kc + kc0) * 16;
                ldsm2(bh[nf], bd);
            }
#pragma unroll
            for (int mf = 0; mf < 4; ++mf)
#pragma unroll
                for (int nf = 0; nf < 4; ++nf) mma16816(acc[mf][nf], ah[mf], bh[nf]);
        }
    }

#pragma unroll
    for (int mf = 0; mf < 4; ++mf) {
#pragma unroll
        for (int half = 0; half < 2; ++half) {
            int row = m0 + m_off + mf * 16 + half * 8 + (lane >> 2);
            float* cr = C + (size_t)row * BIS + c0 + n_off + (lane & 3) * 2;
#pragma unroll
            for (int nf = 0; nf < 4; ++nf) {
                float2 v = make_float2(acc[mf][nf][half * 2], acc[mf][nf][half * 2 + 1]);
                *(float2*)(cr + nf * 8) = v;
            }
        }
    }
}

// ---------------- 7. per-node generated weights + bias ----------------------
__global__ void k_weights(const float* __restrict__ E1, const float* __restrict__ E2,
                          const float* __restrict__ Wp, const float* __restrict__ Wp2,
                          const float* __restrict__ bp, const float* __restrict__ bp2) {
    int n = blockIdx.x, tid = threadIdx.x;
    __shared__ float e1[EE], e2[EE];
    if (tid < EE) e1[tid] = E1[n * EE + tid];
    else if (tid < 2 * EE) e2[tid - EE] = E2[n * EE + tid - EE];
    __syncthreads();
    float l1[EE], l2[EE];
#pragma unroll
    for (int d = 0; d < EE; ++d) { l1[d] = e1[d]; l2[d] = e2[d]; }
    for (int q = tid; q < PW; q += 256) {
        float acc = 0.f;
#pragma unroll
        for (int d = 0; d < EE; ++d)
            acc = fmaf(l1[d], Wp[d * PW + q], fmaf(l2[d], Wp2[d * PW + q], acc));
        g_W[(size_t)n * PW + q] = acc;
    }
    if (tid < OO) {
        float acc = 0.f;
#pragma unroll
        for (int d = 0; d < EE; ++d)
            acc = fmaf(l1[d], bp[d * OO + tid], fmaf(l2[d], bp2[d * OO + tid], acc));
        g_bias[n * OO + tid] = acc;
    }
}

// -------- 8. gconv (hop0 straight from x) -----------------------------------
__global__ __launch_bounds__(384) void k_gconv(const float* __restrict__ x,
                                               float* __restrict__ out) {
    int n = blockIdx.x, tid = threadIdx.x;
    __shared__ float Ws[PW];
    __shared__ float bsh[OO];
    for (int q = tid; q < PW; q += 384) Ws[q] = g_W[(size_t)n * PW + q];
    if (tid < OO) bsh[tid] = g_bias[n * OO + tid];
    __syncthreads();
    int b = tid / SS, s = tid - b * SS;
    float acc[OO];
#pragma unroll
    for (int o = 0; o < OO; ++o) acc[o] = bsh[o];

    // hop 0: x[b,i,n,s]
    {
        const float* yb = x + ((size_t)(b * II) * NN + n) * SS + s;
        const float* wk = Ws;
#pragma unroll 4
        for (int i = 0; i < II; ++i) {
            float v = yb[(size_t)i * NN * SS];
            const float* wr = wk + i * OO;
#pragma unroll
            for (int o = 0; o < OO; ++o) acc[o] = fmaf(v, wr[o], acc[o]);
        }
    }
    // hops 1,2: Y1, Y2 [n][(b,i,s)]
    const float* Yb[2] = { g_Y1, g_Y2 };
#pragma unroll
    for (int k = 0; k < 2; ++k) {
        const float* yb = Yb[k] + (size_t)n * BIS + (size_t)b * II * SS + s;
        const float* wk = Ws + (k + 1) * II * OO;
#pragma unroll 4
        for (int i = 0; i < II; ++i) {
            float v = yb[i * SS];
            const float* wr = wk + i * OO;
#pragma unroll
            for (int o = 0; o < OO; ++o) acc[o] = fmaf(v, wr[o], acc[o]);
        }
    }
#pragma unroll
    for (int o = 0; o < OO; ++o)
        out[(((size_t)b * OO + o) * NN + n) * SS + s] = acc[o];
}

// ---------------------------------------------------------------------------
extern "C" void kernel_launch(void* const* d_in, const int* in_sizes, int n_in,
                              void* d_out, int out_size) {
    const float* x    = (const float*)d_in[0];
    const float* E1   = (const float*)d_in[1];
    const float* E2   = (const float*)d_in[2];
    const float* Wp   = (const float*)d_in[3];
    const float* Wp2  = (const float*)d_in[4];
    const float* bp   = (const float*)d_in[5];
    const float* bp2  = (const float*)d_in[6];
    const float* fc0w = (const float*)d_in[7];
    const float* fc0b = (const float*)d_in[8];
    const float* fc1w = (const float*)d_in[9];
    const float* fc1b = (const float*)d_in[10];
    const float* fc2w = (const float*)d_in[11];
    const float* fc2b = (const float*)d_in[12];
    float* out = (float*)d_out;

    cudaFuncSetAttribute(k_mma1, cudaFuncAttributeMaxDynamicSharedMemorySize, SMTOT);
    cudaFuncSetAttribute(k_mma2, cudaFuncAttributeMaxDynamicSharedMemorySize, SMTOT2);

    k_h1<<<II * NN / 256, 256>>>(x, fc0w, fc0b);
    k_h2<<<II * EE, 256>>>(fc1w, fc1b);
    k_m<<<1, 256>>>(fc2w, fc2b);
    k_adj<<<NN / 4, 128>>>(E1, E2);

    k_split0<<<dim3(BB * II, NN / 256), 256>>>(x);     // x -> B0h/B0l

    dim3 gg(NN / 128, BIS / 128);
    k_mma1<<<gg, 256, SMTOT>>>();                      // Y1 = S @ X
    k_split1<<<dim3(BIS / 32, NN / 32), 256>>>();      // Y1^T -> B1h
    k_mma2<<<gg, 256, SMTOT2>>>();                     // Y2 = S @ Y1

    k_weights<<<NN, 256>>>(E1, E2, Wp, Wp2, bp, bp2);
    k_gconv<<<NN, 384>>>(x, out);
}

// round 11
// speedup vs baseline: 4.3321x; 1.2679x over previous
#include <cuda_runtime.h>
#include <cuda_fp16.h>
#include <cstdint>

#define NN   2048
#define BB   32
#define II   32
#define OO   32
#define SS   12
#define EE   16
#define KK   3          // K+1 hops
#define BIS  12288      // B*II*SS
#define PW   (KK*II*OO)

// ---------------- scratch (device globals) ----------------------------------
__device__ float g_h1[II * NN];
__device__ float g_h2[II * EE];
__device__ float g_m[EE * EE];
__device__ float g_W[(size_t)NN * PW];
__device__ float g_bias[NN * OO];
// fp16 operands / results
__device__ __align__(16) __half g_Ah[(size_t)NN * NN];    // S        [n][k]
__device__ __align__(16) __half g_B0h[(size_t)BIS * NN];  // X^T      [col][k]
__device__ __align__(16) __half g_B1h[(size_t)BIS * NN];  // Y1^T     [col][k]
__device__ __align__(16) __half g_Y1h[(size_t)NN * BIS];  // Y1       [n][col]
__device__ __align__(16) __half g_Y2h[(size_t)NN * BIS];  // Y2       [n][col]

// ---------------- helpers ----------------------------------------------------
__device__ __forceinline__ uint32_t smem_u32(const void* p) {
    uint32_t a;
    asm("{ .reg .u64 t; cvta.to.shared.u64 t, %1; cvt.u32.u64 %0, t; }" : "=r"(a) : "l"(p));
    return a;
}
__device__ __forceinline__ void cp16(uint32_t dst, const void* src) {
    asm volatile("cp.async.cg.shared.global [%0], [%1], 16;" :: "r"(dst), "l"(src) : "memory");
}
#define CP_COMMIT() asm volatile("cp.async.commit_group;" ::: "memory")
#define CP_WAIT2()  asm volatile("cp.async.wait_group 2;" ::: "memory")
#define CP_WAIT0()  asm volatile("cp.async.wait_group 0;" ::: "memory")

__device__ __forceinline__ void ldsm4(uint32_t* r, uint32_t addr) {
    asm volatile("ldmatrix.sync.aligned.m8n8.x4.shared.b16 {%0,%1,%2,%3}, [%4];"
                 : "=r"(r[0]), "=r"(r[1]), "=r"(r[2]), "=r"(r[3]) : "r"(addr));
}
__device__ __forceinline__ void ldsm2(uint32_t* r, uint32_t addr) {
    asm volatile("ldmatrix.sync.aligned.m8n8.x2.shared.b16 {%0,%1}, [%2];"
                 : "=r"(r[0]), "=r"(r[1]) : "r"(addr));
}
__device__ __forceinline__ void mma16816(float* c, const uint32_t* a, const uint32_t* b) {
    asm volatile(
        "mma.sync.aligned.m16n8k16.row.col.f32.f16.f16.f32 "
        "{%0,%1,%2,%3}, {%4,%5,%6,%7}, {%8,%9}, {%0,%1,%2,%3};"
        : "+f"(c[0]), "+f"(c[1]), "+f"(c[2]), "+f"(c[3])
        : "r"(a[0]), "r"(a[1]), "r"(a[2]), "r"(a[3]), "r"(b[0]), "r"(b[1]));
}

// ---------------- 1. h1 -----------------------------------------------------
__global__ void k_h1(const float* __restrict__ x,
                     const float* __restrict__ fc0w,
                     const float* __restrict__ fc0b) {
    int idx = blockIdx.x * 256 + threadIdx.x;
    float acc = fc0b[0];
    const float* xr = x + (size_t)idx * SS;
#pragma unroll
    for (int s = 0; s < SS; ++s) acc = fmaf(xr[s], fc0w[s], acc);
    g_h1[idx] = tanhf(acc);
}

// ---------------- 2. h2 -----------------------------------------------------
__global__ void k_h2(const float* __restrict__ fc1w,
                     const float* __restrict__ fc1b) {
    int i = blockIdx.x >> 4;
    int d = blockIdx.x & 15;
    int tid = threadIdx.x;
    float p = 0.f;
    for (int n = tid; n < NN; n += 256)
        p = fmaf(g_h1[i * NN + n], fc1w[d * NN + n], p);
    __shared__ float red[256];
    red[tid] = p; __syncthreads();
    for (int st = 128; st > 0; st >>= 1) {
        if (tid < st) red[tid] += red[tid + st];
        __syncthreads();
    }
    if (tid == 0) g_h2[i * EE + d] = tanhf(red[0] + fc1b[d]);
}

// ---------------- 3. m ------------------------------------------------------
__global__ void k_m(const float* __restrict__ fc2w,
                    const float* __restrict__ fc2b) {
    int t = threadIdx.x;
    int d = t >> 4, e = t & 15;
    float acc = fc2b[e];
#pragma unroll
    for (int i = 0; i < II; ++i) acc = fmaf(g_h2[i * EE + d], fc2w[e * II + i], acc);
    g_m[d * EE + e] = tanhf(acc);
}

// ------- 4. adjacency softmax -> fp16 (warp-per-row) ------------------------
__global__ __launch_bounds__(128) void k_adj(const float* __restrict__ E1,
                                             const float* __restrict__ E2) {
    __shared__ float buf[4][NN];
    int w = threadIdx.x >> 5, lane = threadIdx.x & 31;
    int n = blockIdx.x * 4 + w;

    float pv = 0.f;
    if (lane < EE) {
#pragma unroll
        for (int d = 0; d < EE; ++d) pv = fmaf(E1[n * EE + d], g_m[d * EE + lane], pv);
    }
    float pl[EE];
#pragma unroll
    for (int e = 0; e < EE; ++e) pl[e] = __shfl_sync(0xffffffffu, pv, e);

    float lmax = 0.f;   // relu => logits >= 0
    for (int mc = lane; mc < NN; mc += 32) {
        const float4* er = (const float4*)(E2 + mc * EE);
        float4 q0 = er[0], q1 = er[1], q2 = er[2], q3 = er[3];
        float a = 0.f;
        a = fmaf(pl[0], q0.x, a);  a = fmaf(pl[1], q0.y, a);
        a = fmaf(pl[2], q0.z, a);  a = fmaf(pl[3], q0.w, a);
        a = fmaf(pl[4], q1.x, a);  a = fmaf(pl[5], q1.y, a);
        a = fmaf(pl[6], q1.z, a);  a = fmaf(pl[7], q1.w, a);
        a = fmaf(pl[8], q2.x, a);  a = fmaf(pl[9], q2.y, a);
        a = fmaf(pl[10], q2.z, a); a = fmaf(pl[11], q2.w, a);
        a = fmaf(pl[12], q3.x, a); a = fmaf(pl[13], q3.y, a);
        a = fmaf(pl[14], q3.z, a); a = fmaf(pl[15], q3.w, a);
        a = fmaxf(a, 0.f);
        buf[w][mc] = a;
        lmax = fmaxf(lmax, a);
    }
#pragma unroll
    for (int o = 16; o; o >>= 1) lmax = fmaxf(lmax, __shfl_xor_sync(0xffffffffu, lmax, o));

    float lsum = 0.f;
    for (int mc = lane; mc < NN; mc += 32) {
        float v = __expf(buf[w][mc] - lmax);
        buf[w][mc] = v;
        lsum += v;
    }
#pragma unroll
    for (int o = 16; o; o >>= 1) lsum += __shfl_xor_sync(0xffffffffu, lsum, o);
    float inv = 1.0f / lsum;

    for (int mc = lane; mc < NN; mc += 32)
        g_Ah[(size_t)n * NN + mc] = __float2half_rn(buf[w][mc] * inv);
}

// --------- 5. B0h = fp16(x^T):  B0[(b,i,s)][m] = x[b,i,m,s] ----------------
__global__ __launch_bounds__(256) void k_split0(const float* __restrict__ x) {
    int bi = blockIdx.x;
    int m = blockIdx.y * 256 + threadIdx.x;
    const float* src = x + ((size_t)bi * NN + m) * SS;
    float v[SS];
#pragma unroll
    for (int s = 0; s < SS; ++s) v[s] = src[s];
#pragma unroll
    for (int s = 0; s < SS; ++s)
        g_B0h[(size_t)(bi * SS + s) * NN + m] = __float2half_rn(v[s]);
}

// ============== GEMM core defs ==============================================
#define ROWB 80
#define MATSZ (128 * ROWB)      // 10240 B per matrix tile
#define STG2  (2 * MATSZ)       // A, B  = 20480
#define NSTG2 4
#define SMTOT2 (NSTG2 * STG2)   // 81920
#define NCHUNK (NN / 32)
#define ROWP 132                // fp16 transpose-staging row pitch

// ============== 6a. GEMM1  Y1 = S @ X  (1-term), fused transposed outputs ===
__global__ __launch_bounds__(256, 1) void k_mma1() {
    extern __shared__ char smem[];
    const uint32_t sb = smem_u32(smem);
    const int tid = threadIdx.x;
    const int lane = tid & 31;
    const int warp = tid >> 5;
    const int m_off = (warp & 1) * 64;
    const int n_off = (warp >> 1) * 32;

    const char* pAh = (const char*)g_Ah;
    const char* pBh = (const char*)g_B0h;

    const int m0 = blockIdx.x * 128;
    const int c0 = blockIdx.y * 128;

    auto load_stage = [&](int stg, int chunk) {
        const uint32_t base = sb + stg * STG2;
        const int k0 = chunk * 32;
#pragma unroll
        for (int r = 0; r < 4; ++r) {
            int id = tid + r * 256;
            int mat = id >> 9;
            int rid = id & 511;
            int row = rid >> 2;
            int cc = rid & 3;
            uint32_t so = base + mat * MATSZ + row * ROWB + cc * 16;
            size_t go;
            const char* p;
            if (mat == 0) { go = ((size_t)(m0 + row) * NN + k0 + cc * 8) * 2; p = pAh; }
            else          { go = ((size_t)(c0 + row) * NN + k0 + cc * 8) * 2; p = pBh; }
            cp16(so, p + go);
        }
    };

    float acc[4][4][4];
#pragma unroll
    for (int i = 0; i < 4; ++i)
#pragma unroll
        for (int j = 0; j < 4; ++j)
#pragma unroll
            for (int q = 0; q < 4; ++q) acc[i][j][q] = 0.f;

    load_stage(0, 0); CP_COMMIT();
    load_stage(1, 1); CP_COMMIT();
    load_stage(2, 2); CP_COMMIT();

    const int grp = lane >> 3, lr = lane & 7;
    const int a_row_base = m_off + (grp & 1) * 8 + lr;
    const int a_kc = grp >> 1;
    const int b_row_base = n_off + lr;
    const int b_kc = grp & 1;

    for (int c = 0; c < NCHUNK; ++c) {
        const int st = c & 3;
        if (c + 1 < NCHUNK) CP_WAIT2(); else CP_WAIT0();
        __syncthreads();
        if (c + 3 < NCHUNK) load_stage((c + 3) & 3, c + 3);
        CP_COMMIT();

        const uint32_t base = sb + st * STG2;
#pragma unroll
        for (int ks = 0; ks < 2; ++ks) {
            const int kc0 = ks * 2;
            uint32_t ah[4][4], bh[4][2];
#pragma unroll
            for (int mf = 0; mf < 4; ++mf) {
                uint32_t ad = base + (a_row_base + mf * 16) * ROWB + (a_kc + kc0) * 16;
                ldsm4(ah[mf], ad);
            }
#pragma unroll
            for (int nf = 0; nf < 4; ++nf) {
                uint32_t bd = base + MATSZ + (b_row_base + nf * 8) * ROWB + (b_kc + kc0) * 16;
                ldsm2(bh[nf], bd);
            }
#pragma unroll
            for (int mf = 0; mf < 4; ++mf)
#pragma unroll
                for (int nf = 0; nf < 4; ++nf) mma16816(acc[mf][nf], ah[mf], bh[nf]);
        }
    }

    // ---- fused epilogue: g_Y1h [row][col] + smem-transposed g_B1h [col][row]
    __syncthreads();                 // all ldsm of final stage complete
    __half* sh = (__half*)smem;
#pragma unroll
    for (int mf = 0; mf < 4; ++mf) {
#pragma unroll
        for (int half = 0; half < 2; ++half) {
            int rowL = m_off + mf * 16 + half * 8 + (lane >> 2);
            __half* yr = g_Y1h + (size_t)(m0 + rowL) * BIS + c0;
#pragma unroll
            for (int nf = 0; nf < 4; ++nf) {
                int colL = n_off + nf * 8 + (lane & 3) * 2;
                __half h0 = __float2half_rn(acc[mf][nf][half * 2]);
                __half h1 = __float2half_rn(acc[mf][nf][half * 2 + 1]);
                *(__half2*)(yr + colL) = __halves2half2(h0, h1);
                sh[colL * ROWP + rowL] = h0;
                sh[(colL + 1) * ROWP + rowL] = h1;
            }
        }
    }
    __syncthreads();
    {
        int col = tid >> 1;           // 128 cols
        int rh = tid & 1;             // 64-row half
        const __half* srow = sh + col * ROWP + rh * 64;
        __half* drow = g_B1h + (size_t)(c0 + col) * NN + m0 + rh * 64;
#pragma unroll
        for (int q = 0; q < 16; ++q)  // 64 halfs = 16 x 8B
            *(uint2*)(drow + q * 4) = *(const uint2*)(srow + q * 4);
    }
}

// ============== 6b. GEMM2  Y2 = S @ Y1  (1-term), fp16 out ==================
__global__ __launch_bounds__(256, 1) void k_mma2() {
    extern __shared__ char smem[];
    const uint32_t sb = smem_u32(smem);
    const int tid = threadIdx.x;
    const int lane = tid & 31;
    const int warp = tid >> 5;
    const int m_off = (warp & 1) * 64;
    const int n_off = (warp >> 1) * 32;

    const char* pAh = (const char*)g_Ah;
    const char* pBh = (const char*)g_B1h;

    const int m0 = blockIdx.x * 128;
    const int c0 = blockIdx.y * 128;

    auto load_stage = [&](int stg, int chunk) {
        const uint32_t base = sb + stg * STG2;
        const int k0 = chunk * 32;
#pragma unroll
        for (int r = 0; r < 4; ++r) {
            int id = tid + r * 256;
            int mat = id >> 9;
            int rid = id & 511;
            int row = rid >> 2;
            int cc = rid & 3;
            uint32_t so = base + mat * MATSZ + row * ROWB + cc * 16;
            size_t go;
            const char* p;
            if (mat == 0) { go = ((size_t)(m0 + row) * NN + k0 + cc * 8) * 2; p = pAh; }
            else          { go = ((size_t)(c0 + row) * NN + k0 + cc * 8) * 2; p = pBh; }
            cp16(so, p + go);
        }
    };

    float acc[4][4][4];
#pragma unroll
    for (int i = 0; i < 4; ++i)
#pragma unroll
        for (int j = 0; j < 4; ++j)
#pragma unroll
            for (int q = 0; q < 4; ++q) acc[i][j][q] = 0.f;

    load_stage(0, 0); CP_COMMIT();
    load_stage(1, 1); CP_COMMIT();
    load_stage(2, 2); CP_COMMIT();

    const int grp = lane >> 3, lr = lane & 7;
    const int a_row_base = m_off + (grp & 1) * 8 + lr;
    const int a_kc = grp >> 1;
    const int b_row_base = n_off + lr;
    const int b_kc = grp & 1;

    for (int c = 0; c < NCHUNK; ++c) {
        const int st = c & 3;
        if (c + 1 < NCHUNK) CP_WAIT2(); else CP_WAIT0();
        __syncthreads();
        if (c + 3 < NCHUNK) load_stage((c + 3) & 3, c + 3);
        CP_COMMIT();

        const uint32_t base = sb + st * STG2;
#pragma unroll
        for (int ks = 0; ks < 2; ++ks) {
            const int kc0 = ks * 2;
            uint32_t ah[4][4], bh[4][2];
#pragma unroll
            for (int mf = 0; mf < 4; ++mf) {
                uint32_t ad = base + (a_row_base + mf * 16) * ROWB + (a_kc + kc0) * 16;
                ldsm4(ah[mf], ad);
            }
#pragma unroll
            for (int nf = 0; nf < 4; ++nf) {
                uint32_t bd = base + MATSZ + (b_row_base + nf * 8) * ROWB + (b_kc + kc0) * 16;
                ldsm2(bh[nf], bd);
            }
#pragma unroll
            for (int mf = 0; mf < 4; ++mf)
#pragma unroll
                for (int nf = 0; nf < 4; ++nf) mma16816(acc[mf][nf], ah[mf], bh[nf]);
        }
    }

#pragma unroll
    for (int mf = 0; mf < 4; ++mf) {
#pragma unroll
        for (int half = 0; half < 2; ++half) {
            int rowL = m_off + mf * 16 + half * 8 + (lane >> 2);
            __half* yr = g_Y2h + (size_t)(m0 + rowL) * BIS + c0;
#pragma unroll
            for (int nf = 0; nf < 4; ++nf) {
                int colL = n_off + nf * 8 + (lane & 3) * 2;
                __half h0 = __float2half_rn(acc[mf][nf][half * 2]);
                __half h1 = __float2half_rn(acc[mf][nf][half * 2 + 1]);
                *(__half2*)(yr + colL) = __halves2half2(h0, h1);
            }
        }
    }
}

// ---------------- 7. per-node generated weights + bias ----------------------
__global__ void k_weights(const float* __restrict__ E1, const float* __restrict__ E2,
                          const float* __restrict__ Wp, const float* __restrict__ Wp2,
                          const float* __restrict__ bp, const float* __restrict__ bp2) {
    int n = blockIdx.x, tid = threadIdx.x;
    __shared__ float e1[EE], e2[EE];
    if (tid < EE) e1[tid] = E1[n * EE + tid];
    else if (tid < 2 * EE) e2[tid - EE] = E2[n * EE + tid - EE];
    __syncthreads();
    float l1[EE], l2[EE];
#pragma unroll
    for (int d = 0; d < EE; ++d) { l1[d] = e1[d]; l2[d] = e2[d]; }
    for (int q = tid; q < PW; q += 256) {
        float acc = 0.f;
#pragma unroll
        for (int d = 0; d < EE; ++d)
            acc = fmaf(l1[d], Wp[d * PW + q], fmaf(l2[d], Wp2[d * PW + q], acc));
        g_W[(size_t)n * PW + q] = acc;
    }
    if (tid < OO) {
        float acc = 0.f;
#pragma unroll
        for (int d = 0; d < EE; ++d)
            acc = fmaf(l1[d], bp[d * OO + tid], fmaf(l2[d], bp2[d * OO + tid], acc));
        g_bias[n * OO + tid] = acc;
    }
}

// -------- 8. gconv (hop0 from x fp32; hops 1,2 from fp16) -------------------
__global__ __launch_bounds__(384) void k_gconv(const float* __restrict__ x,
                                               float* __restrict__ out) {
    int n = blockIdx.x, tid = threadIdx.x;
    __shared__ float Ws[PW];
    __shared__ float bsh[OO];
    for (int q = tid; q < PW; q += 384) Ws[q] = g_W[(size_t)n * PW + q];
    if (tid < OO) bsh[tid] = g_bias[n * OO + tid];
    __syncthreads();
    int b = tid / SS, s = tid - b * SS;
    float acc[OO];
#pragma unroll
    for (int o = 0; o < OO; ++o) acc[o] = bsh[o];

    // hop 0: x[b,i,n,s] fp32
    {
        const float* yb = x + ((size_t)(b * II) * NN + n) * SS + s;
        const float* wk = Ws;
#pragma unroll 4
        for (int i = 0; i < II; ++i) {
            float v = yb[(size_t)i * NN * SS];
            const float* wr = wk + i * OO;
#pragma unroll
            for (int o = 0; o < OO; ++o) acc[o] = fmaf(v, wr[o], acc[o]);
        }
    }
    // hops 1,2: Y1h, Y2h [n][(b,i,s)] fp16
    const __half* Yb[2] = { g_Y1h, g_Y2h };
#pragma unroll
    for (int k = 0; k < 2; ++k) {
        const __half* yb = Yb[k] + (size_t)n * BIS + (size_t)b * II * SS + s;
        const float* wk = Ws + (k + 1) * II * OO;
#pragma unroll 4
        for (int i = 0; i < II; ++i) {
            float v = __half2float(yb[i * SS]);
            const float* wr = wk + i * OO;
#pragma unroll
            for (int o = 0; o < OO; ++o) acc[o] = fmaf(v, wr[o], acc[o]);
        }
    }
#pragma unroll
    for (int o = 0; o < OO; ++o)
        out[(((size_t)b * OO + o) * NN + n) * SS + s] = acc[o];
}

// ---------------------------------------------------------------------------
extern "C" void kernel_launch(void* const* d_in, const int* in_sizes, int n_in,
                              void* d_out, int out_size) {
    const float* x    = (const float*)d_in[0];
    const float* E1   = (const float*)d_in[1];
    const float* E2   = (const float*)d_in[2];
    const float* Wp   = (const float*)d_in[3];
    const float* Wp2  = (const float*)d_in[4];
    const float* bp   = (const float*)d_in[5];
    const float* bp2  = (const float*)d_in[6];
    const float* fc0w = (const float*)d_in[7];
    const float* fc0b = (const float*)d_in[8];
    const float* fc1w = (const float*)d_in[9];
    const float* fc1b = (const float*)d_in[10];
    const float* fc2w = (const float*)d_in[11];
    const float* fc2b = (const float*)d_in[12];
    float* out = (float*)d_out;

    cudaFuncSetAttribute(k_mma1, cudaFuncAttributeMaxDynamicSharedMemorySize, SMTOT2);
    cudaFuncSetAttribute(k_mma2, cudaFuncAttributeMaxDynamicSharedMemorySize, SMTOT2);

    k_h1<<<II * NN / 256, 256>>>(x, fc0w, fc0b);
    k_h2<<<II * EE, 256>>>(fc1w, fc1b);
    k_m<<<1, 256>>>(fc2w, fc2b);
    k_adj<<<NN / 4, 128>>>(E1, E2);

    k_split0<<<dim3(BB * II, NN / 256), 256>>>(x);     // x -> B0h

    dim3 gg(NN / 128, BIS / 128);
    k_mma1<<<gg, 256, SMTOT2>>>();                     // Y1h + B1h (fused)
    k_mma2<<<gg, 256, SMTOT2>>>();                     // Y2h

    k_weights<<<NN, 256>>>(E1, E2, Wp, Wp2, bp, bp2);
    k_gconv<<<NN, 384>>>(x, out);
}

// round 12
// speedup vs baseline: 4.6868x; 1.0819x over previous
#include <cuda_runtime.h>
#include <cuda_fp16.h>
#include <cstdint>

#define NN   2048
#define BB   32
#define II   32
#define OO   32
#define SS   12
#define EE   16
#define KK   3          // K+1 hops
#define BIS  12288      // B*II*SS
#define PW   (KK*II*OO)

// ---------------- scratch (device globals) ----------------------------------
__device__ float g_h1[II * NN];
__device__ float g_h2[II * EE];
__device__ float g_m[EE * EE];
__device__ float g_W[(size_t)NN * PW];
__device__ float g_bias[NN * OO];
// fp16 operands / results
__device__ __align__(16) __half g_Ah[(size_t)NN * NN];    // S        [n][k]
__device__ __align__(16) __half g_B0h[(size_t)BIS * NN];  // X^T      [col][k]
__device__ __align__(16) __half g_B1h[(size_t)BIS * NN];  // Y1^T     [col][k]
__device__ __align__(16) __half g_Y1h[(size_t)NN * BIS];  // Y1       [n][col]
__device__ __align__(16) __half g_Y2h[(size_t)NN * BIS];  // Y2       [n][col]

// ---------------- helpers ----------------------------------------------------
__device__ __forceinline__ uint32_t smem_u32(const void* p) {
    uint32_t a;
    asm("{ .reg .u64 t; cvta.to.shared.u64 t, %1; cvt.u32.u64 %0, t; }" : "=r"(a) : "l"(p));
    return a;
}
__device__ __forceinline__ void cp16(uint32_t dst, const void* src) {
    asm volatile("cp.async.cg.shared.global [%0], [%1], 16;" :: "r"(dst), "l"(src) : "memory");
}
#define CP_COMMIT() asm volatile("cp.async.commit_group;" ::: "memory")
#define CP_WAIT2()  asm volatile("cp.async.wait_group 2;" ::: "memory")
#define CP_WAIT0()  asm volatile("cp.async.wait_group 0;" ::: "memory")

__device__ __forceinline__ void ldsm4(uint32_t* r, uint32_t addr) {
    asm volatile("ldmatrix.sync.aligned.m8n8.x4.shared.b16 {%0,%1,%2,%3}, [%4];"
                 : "=r"(r[0]), "=r"(r[1]), "=r"(r[2]), "=r"(r[3]) : "r"(addr));
}
__device__ __forceinline__ void mma16816(float* c, const uint32_t* a, const uint32_t* b) {
    asm volatile(
        "mma.sync.aligned.m16n8k16.row.col.f32.f16.f16.f32 "
        "{%0,%1,%2,%3}, {%4,%5,%6,%7}, {%8,%9}, {%0,%1,%2,%3};"
        : "+f"(c[0]), "+f"(c[1]), "+f"(c[2]), "+f"(c[3])
        : "r"(a[0]), "r"(a[1]), "r"(a[2]), "r"(a[3]), "r"(b[0]), "r"(b[1]));
}

// ---------------- 1. h1 -----------------------------------------------------
__global__ void k_h1(const float* __restrict__ x,
                     const float* __restrict__ fc0w,
                     const float* __restrict__ fc0b) {
    int idx = blockIdx.x * 256 + threadIdx.x;
    float acc = fc0b[0];
    const float* xr = x + (size_t)idx * SS;
#pragma unroll
    for (int s = 0; s < SS; ++s) acc = fmaf(xr[s], fc0w[s], acc);
    g_h1[idx] = tanhf(acc);
}

// ---------------- 2. h2 -----------------------------------------------------
__global__ void k_h2(const float* __restrict__ fc1w,
                     const float* __restrict__ fc1b) {
    int i = blockIdx.x >> 4;
    int d = blockIdx.x & 15;
    int tid = threadIdx.x;
    float p = 0.f;
    for (int n = tid; n < NN; n += 256)
        p = fmaf(g_h1[i * NN + n], fc1w[d * NN + n], p);
    __shared__ float red[256];
    red[tid] = p; __syncthreads();
    for (int st = 128; st > 0; st >>= 1) {
        if (tid < st) red[tid] += red[tid + st];
        __syncthreads();
    }
    if (tid == 0) g_h2[i * EE + d] = tanhf(red[0] + fc1b[d]);
}

// ---------------- 3. m ------------------------------------------------------
__global__ void k_m(const float* __restrict__ fc2w,
                    const float* __restrict__ fc2b) {
    int t = threadIdx.x;
    int d = t >> 4, e = t & 15;
    float acc = fc2b[e];
#pragma unroll
    for (int i = 0; i < II; ++i) acc = fmaf(g_h2[i * EE + d], fc2w[e * II + i], acc);
    g_m[d * EE + e] = tanhf(acc);
}

// ------- 4. adjacency softmax -> fp16 (warp-per-row) ------------------------
__global__ __launch_bounds__(128) void k_adj(const float* __restrict__ E1,
                                             const float* __restrict__ E2) {
    __shared__ float buf[4][NN];
    int w = threadIdx.x >> 5, lane = threadIdx.x & 31;
    int n = blockIdx.x * 4 + w;

    float pv = 0.f;
    if (lane < EE) {
#pragma unroll
        for (int d = 0; d < EE; ++d) pv = fmaf(E1[n * EE + d], g_m[d * EE + lane], pv);
    }
    float pl[EE];
#pragma unroll
    for (int e = 0; e < EE; ++e) pl[e] = __shfl_sync(0xffffffffu, pv, e);

    float lmax = 0.f;   // relu => logits >= 0
    for (int mc = lane; mc < NN; mc += 32) {
        const float4* er = (const float4*)(E2 + mc * EE);
        float4 q0 = er[0], q1 = er[1], q2 = er[2], q3 = er[3];
        float a = 0.f;
        a = fmaf(pl[0], q0.x, a);  a = fmaf(pl[1], q0.y, a);
        a = fmaf(pl[2], q0.z, a);  a = fmaf(pl[3], q0.w, a);
        a = fmaf(pl[4], q1.x, a);  a = fmaf(pl[5], q1.y, a);
        a = fmaf(pl[6], q1.z, a);  a = fmaf(pl[7], q1.w, a);
        a = fmaf(pl[8], q2.x, a);  a = fmaf(pl[9], q2.y, a);
        a = fmaf(pl[10], q2.z, a); a = fmaf(pl[11], q2.w, a);
        a = fmaf(pl[12], q3.x, a); a = fmaf(pl[13], q3.y, a);
        a = fmaf(pl[14], q3.z, a); a = fmaf(pl[15], q3.w, a);
        a = fmaxf(a, 0.f);
        buf[w][mc] = a;
        lmax = fmaxf(lmax, a);
    }
#pragma unroll
    for (int o = 16; o; o >>= 1) lmax = fmaxf(lmax, __shfl_xor_sync(0xffffffffu, lmax, o));

    float lsum = 0.f;
    for (int mc = lane; mc < NN; mc += 32) {
        float v = __expf(buf[w][mc] - lmax);
        buf[w][mc] = v;
        lsum += v;
    }
#pragma unroll
    for (int o = 16; o; o >>= 1) lsum += __shfl_xor_sync(0xffffffffu, lsum, o);
    float inv = 1.0f / lsum;

    for (int mc = lane; mc < NN; mc += 32)
        g_Ah[(size_t)n * NN + mc] = __float2half_rn(buf[w][mc] * inv);
}

// --------- 5. B0h = fp16(x^T):  B0[(b,i,s)][m] = x[b,i,m,s] ----------------
__global__ __launch_bounds__(256) void k_split0(const float* __restrict__ x) {
    int bi = blockIdx.x;
    int m = blockIdx.y * 256 + threadIdx.x;
    const float* src = x + ((size_t)bi * NN + m) * SS;
    float v[SS];
#pragma unroll
    for (int s = 0; s < SS; ++s) v[s] = src[s];
#pragma unroll
    for (int s = 0; s < SS; ++s)
        g_B0h[(size_t)(bi * SS + s) * NN + m] = __float2half_rn(v[s]);
}

// ============== GEMM core defs ==============================================
// BM=128, BN=256, BK=32; warp tile 64x64 (8 warps = 2m x 4n)
#define ROWB 80
#define MATSZ_A (128 * ROWB)    // 10240
#define MATSZ_B (256 * ROWB)    // 20480
#define STG   (MATSZ_A + MATSZ_B)   // 30720
#define NSTG  4
#define SMTOT (NSTG * STG)      // 122880
#define NCHUNK (NN / 32)
#define ROWP 132                // fp16 transpose-staging row pitch

// common GEMM body: computes acc for one 128x256 tile of C = Ah @ B^T
#define GEMM_BODY(pB)                                                           \
    const char* pAh = (const char*)g_Ah;                                        \
    const char* pBh = (const char*)(pB);                                        \
    const int m0 = blockIdx.x * 128;                                            \
    const int c0 = blockIdx.y * 256;                                            \
    auto load_stage = [&](int stg, int chunk) {                                 \
        const uint32_t base = sb + stg * STG;                                   \
        const int k0 = chunk * 32;                                              \
        _Pragma("unroll")                                                       \
        for (int r = 0; r < 6; ++r) {                                           \
            int id = tid + r * 256;                                             \
            if (id < 512) {                                                     \
                int row = id >> 2, cc = id & 3;                                 \
                cp16(base + row * ROWB + cc * 16,                               \
                     pAh + ((size_t)(m0 + row) * NN + k0 + cc * 8) * 2);        \
            } else {                                                            \
                int idx = id - 512;                                             \
                int row = idx >> 2, cc = idx & 3;                               \
                cp16(base + MATSZ_A + row * ROWB + cc * 16,                     \
                     pBh + ((size_t)(c0 + row) * NN + k0 + cc * 8) * 2);        \
            }                                                                   \
        }                                                                       \
    };                                                                          \
    float acc[4][8][4];                                                         \
    _Pragma("unroll")                                                           \
    for (int i = 0; i < 4; ++i)                                                 \
        _Pragma("unroll")                                                       \
        for (int j = 0; j < 8; ++j)                                             \
            _Pragma("unroll")                                                   \
            for (int q = 0; q < 4; ++q) acc[i][j][q] = 0.f;                     \
    load_stage(0, 0); CP_COMMIT();                                              \
    load_stage(1, 1); CP_COMMIT();                                              \
    load_stage(2, 2); CP_COMMIT();                                              \
    const int grp = lane >> 3, lr = lane & 7;                                   \
    const int a_row_base = m_off + (grp & 1) * 8 + lr;                          \
    const int a_kc = grp >> 1;                                                  \
    const int b_row_base = n_off + (grp >> 1) * 8 + lr;                         \
    const int b_kc = grp & 1;                                                   \
    for (int c = 0; c < NCHUNK; ++c) {                                          \
        const int st = c & 3;                                                   \
        if (c + 1 < NCHUNK) CP_WAIT2(); else CP_WAIT0();                        \
        __syncthreads();                                                        \
        if (c + 3 < NCHUNK) load_stage((c + 3) & 3, c + 3);                     \
        CP_COMMIT();                                                            \
        const uint32_t base = sb + st * STG;                                    \
        _Pragma("unroll")                                                       \
        for (int ks = 0; ks < 2; ++ks) {                                        \
            const int kc0 = ks * 2;                                             \
            uint32_t ah[4][4], bh[4][4];                                        \
            _Pragma("unroll")                                                   \
            for (int mf = 0; mf < 4; ++mf)                                      \
                ldsm4(ah[mf], base + (a_row_base + mf * 16) * ROWB              \
                                  + (a_kc + kc0) * 16);                         \
            _Pragma("unroll")                                                   \
            for (int nf = 0; nf < 4; ++nf)                                      \
                ldsm4(bh[nf], base + MATSZ_A + (b_row_base + nf * 16) * ROWB    \
                                  + (b_kc + kc0) * 16);                         \
            _Pragma("unroll")                                                   \
            for (int mf = 0; mf < 4; ++mf)                                      \
                _Pragma("unroll")                                               \
                for (int nf = 0; nf < 4; ++nf) {                                \
                    mma16816(acc[mf][nf * 2],     ah[mf], &bh[nf][0]);          \
                    mma16816(acc[mf][nf * 2 + 1], ah[mf], &bh[nf][2]);          \
                }                                                               \
        }                                                                       \
    }

// ============== 6a. GEMM1  Y1 = S @ X  -> Y1h + fused B1h transpose =========
__global__ __launch_bounds__(256, 1) void k_mma1() {
    extern __shared__ char smem[];
    const uint32_t sb = smem_u32(smem);
    const int tid = threadIdx.x;
    const int lane = tid & 31;
    const int warp = tid >> 5;
    const int m_off = (warp & 1) * 64;
    const int n_off = (warp >> 1) * 64;

    GEMM_BODY(g_B0h)

    __syncthreads();
    // g_Y1h [row][col]
#pragma unroll
    for (int mf = 0; mf < 4; ++mf) {
#pragma unroll
        for (int half = 0; half < 2; ++half) {
            int rowL = m_off + mf * 16 + half * 8 + (lane >> 2);
            __half* yr = g_Y1h + (size_t)(m0 + rowL) * BIS + c0;
#pragma unroll
            for (int n8 = 0; n8 < 8; ++n8) {
                int colL = n_off + n8 * 8 + (lane & 3) * 2;
                __half h0 = __float2half_rn(acc[mf][n8][half * 2]);
                __half h1 = __float2half_rn(acc[mf][n8][half * 2 + 1]);
                *(__half2*)(yr + colL) = __halves2half2(h0, h1);
            }
        }
    }
    // two-pass smem transpose -> g_B1h [col][row]
    __half* sh = (__half*)smem;
#pragma unroll
    for (int p = 0; p < 2; ++p) {
        __syncthreads();
        if (n_off >= p * 128 && n_off < p * 128 + 128) {
#pragma unroll
            for (int mf = 0; mf < 4; ++mf) {
#pragma unroll
                for (int half = 0; half < 2; ++half) {
                    int rowL = m_off + mf * 16 + half * 8 + (lane >> 2);
#pragma unroll
                    for (int n8 = 0; n8 < 8; ++n8) {
                        int colL = n_off + n8 * 8 + (lane & 3) * 2 - p * 128;
                        sh[colL * ROWP + rowL] =
                            __float2half_rn(acc[mf][n8][half * 2]);
                        sh[(colL + 1) * ROWP + rowL] =
                            __float2half_rn(acc[mf][n8][half * 2 + 1]);
                    }
                }
            }
        }
        __syncthreads();
        int col = tid >> 1, rh = tid & 1;
        const __half* srow = sh + col * ROWP + rh * 64;
        __half* drow = g_B1h + (size_t)(c0 + p * 128 + col) * NN + m0 + rh * 64;
#pragma unroll
        for (int q = 0; q < 16; ++q)
            *(uint2*)(drow + q * 4) = *(const uint2*)(srow + q * 4);
    }
}

// ============== 6b. GEMM2  Y2 = S @ Y1  -> Y2h ==============================
__global__ __launch_bounds__(256, 1) void k_mma2() {
    extern __shared__ char smem[];
    const uint32_t sb = smem_u32(smem);
    const int tid = threadIdx.x;
    const int lane = tid & 31;
    const int warp = tid >> 5;
    const int m_off = (warp & 1) * 64;
    const int n_off = (warp >> 1) * 64;

    GEMM_BODY(g_B1h)

#pragma unroll
    for (int mf = 0; mf < 4; ++mf) {
#pragma unroll
        for (int half = 0; half < 2; ++half) {
            int rowL = m_off + mf * 16 + half * 8 + (lane >> 2);
            __half* yr = g_Y2h + (size_t)(m0 + rowL) * BIS + c0;
#pragma unroll
            for (int n8 = 0; n8 < 8; ++n8) {
                int colL = n_off + n8 * 8 + (lane & 3) * 2;
                __half h0 = __float2half_rn(acc[mf][n8][half * 2]);
                __half h1 = __float2half_rn(acc[mf][n8][half * 2 + 1]);
                *(__half2*)(yr + colL) = __halves2half2(h0, h1);
            }
        }
    }
}

// ---------------- 7. per-node generated weights + bias ----------------------
__global__ void k_weights(const float* __restrict__ E1, const float* __restrict__ E2,
                          const float* __restrict__ Wp, const float* __restrict__ Wp2,
                          const float* __restrict__ bp, const float* __restrict__ bp2) {
    int n = blockIdx.x, tid = threadIdx.x;
    __shared__ float e1[EE], e2[EE];
    if (tid < EE) e1[tid] = E1[n * EE + tid];
    else if (tid < 2 * EE) e2[tid - EE] = E2[n * EE + tid - EE];
    __syncthreads();
    float l1[EE], l2[EE];
#pragma unroll
    for (int d = 0; d < EE; ++d) { l1[d] = e1[d]; l2[d] = e2[d]; }
    for (int q = tid; q < PW; q += 256) {
        float acc = 0.f;
#pragma unroll
        for (int d = 0; d < EE; ++d)
            acc = fmaf(l1[d], Wp[d * PW + q], fmaf(l2[d], Wp2[d * PW + q], acc));
        g_W[(size_t)n * PW + q] = acc;
    }
    if (tid < OO) {
        float acc = 0.f;
#pragma unroll
        for (int d = 0; d < EE; ++d)
            acc = fmaf(l1[d], bp[d * OO + tid], fmaf(l2[d], bp2[d * OO + tid], acc));
        g_bias[n * OO + tid] = acc;
    }
}

// -------- 8. gconv (hop0 from x fp32; hops 1,2 from fp16) -------------------
__global__ __launch_bounds__(384) void k_gconv(const float* __restrict__ x,
                                               float* __restrict__ out) {
    int n = blockIdx.x, tid = threadIdx.x;
    __shared__ float Ws[PW];
    __shared__ float bsh[OO];
    for (int q = tid; q < PW; q += 384) Ws[q] = g_W[(size_t)n * PW + q];
    if (tid < OO) bsh[tid] = g_bias[n * OO + tid];
    __syncthreads();
    int b = tid / SS, s = tid - b * SS;
    float acc[OO];
#pragma unroll
    for (int o = 0; o < OO; ++o) acc[o] = bsh[o];

    // hop 0: x[b,i,n,s] fp32
    {
        const float* yb = x + ((size_t)(b * II) * NN + n) * SS + s;
        const float* wk = Ws;
#pragma unroll 4
        for (int i = 0; i < II; ++i) {
            float v = yb[(size_t)i * NN * SS];
            const float* wr = wk + i * OO;
#pragma unroll
            for (int o = 0; o < OO; ++o) acc[o] = fmaf(v, wr[o], acc[o]);
        }
    }
    // hops 1,2: Y1h, Y2h [n][(b,i,s)] fp16
    const __half* Yb[2] = { g_Y1h, g_Y2h };
#pragma unroll
    for (int k = 0; k < 2; ++k) {
        const __half* yb = Yb[k] + (size_t)n * BIS + (size_t)b * II * SS + s;
        const float* wk = Ws + (k + 1) * II * OO;
#pragma unroll 4
        for (int i = 0; i < II; ++i) {
            float v = __half2float(yb[i * SS]);
            const float* wr = wk + i * OO;
#pragma unroll
            for (int o = 0; o < OO; ++o) acc[o] = fmaf(v, wr[o], acc[o]);
        }
    }
#pragma unroll
    for (int o = 0; o < OO; ++o)
        out[(((size_t)b * OO + o) * NN + n) * SS + s] = acc[o];
}

// ---------------------------------------------------------------------------
extern "C" void kernel_launch(void* const* d_in, const int* in_sizes, int n_in,
                              void* d_out, int out_size) {
    const float* x    = (const float*)d_in[0];
    const float* E1   = (const float*)d_in[1];
    const float* E2   = (const float*)d_in[2];
    const float* Wp   = (const float*)d_in[3];
    const float* Wp2  = (const float*)d_in[4];
    const float* bp   = (const float*)d_in[5];
    const float* bp2  = (const float*)d_in[6];
    const float* fc0w = (const float*)d_in[7];
    const float* fc0b = (const float*)d_in[8];
    const float* fc1w = (const float*)d_in[9];
    const float* fc1b = (const float*)d_in[10];
    const float* fc2w = (const float*)d_in[11];
    const float* fc2b = (const float*)d_in[12];
    float* out = (float*)d_out;

    cudaFuncSetAttribute(k_mma1, cudaFuncAttributeMaxDynamicSharedMemorySize, SMTOT);
    cudaFuncSetAttribute(k_mma2, cudaFuncAttributeMaxDynamicSharedMemorySize, SMTOT);

    k_h1<<<II * NN / 256, 256>>>(x, fc0w, fc0b);
    k_h2<<<II * EE, 256>>>(fc1w, fc1b);
    k_m<<<1, 256>>>(fc2w, fc2b);
    k_adj<<<NN / 4, 128>>>(E1, E2);

    k_split0<<<dim3(BB * II, NN / 256), 256>>>(x);     // x -> B0h

    dim3 gg(NN / 128, BIS / 256);
    k_mma1<<<gg, 256, SMTOT>>>();                      // Y1h + B1h (fused)
    k_mma2<<<gg, 256, SMTOT>>>();                      // Y2h

    k_weights<<<NN, 256>>>(E1, E2, Wp, Wp2, bp, bp2);
    k_gconv<<<NN, 384>>>(x, out);
}

// round 13
// speedup vs baseline: 4.8820x; 1.0416x over previous
#include <cuda_runtime.h>
#include <cuda_fp16.h>
#include <cstdint>

#define NN   2048
#define BB   32
#define II   32
#define OO   32
#define SS   12
#define EE   16
#define KK   3          // K+1 hops
#define BIS  12288      // B*II*SS
#define PW   (KK*II*OO)

// ---------------- scratch (device globals) ----------------------------------
__device__ float g_h1[II * NN];
__device__ float g_h2[II * EE];
__device__ float g_m[EE * EE];
__device__ float g_W[(size_t)NN * PW];
__device__ float g_bias[NN * OO];
// fp16 operands / results
__device__ __align__(16) __half g_Ah[(size_t)NN * NN];    // S        [n][k]
__device__ __align__(16) __half g_B0h[(size_t)BIS * NN];  // X^T      [col][k]
__device__ __align__(16) __half g_B1h[(size_t)BIS * NN];  // Y1^T     [col][k]
__device__ __align__(16) __half g_Y1h[(size_t)NN * BIS];  // Y1       [n][col]
__device__ __align__(16) __half g_Y2h[(size_t)NN * BIS];  // Y2       [n][col]

// ---------------- helpers ----------------------------------------------------
__device__ __forceinline__ uint32_t smem_u32(const void* p) {
    uint32_t a;
    asm("{ .reg .u64 t; cvta.to.shared.u64 t, %1; cvt.u32.u64 %0, t; }" : "=r"(a) : "l"(p));
    return a;
}
__device__ __forceinline__ void cp16(uint32_t dst, const void* src) {
    asm volatile("cp.async.cg.shared.global [%0], [%1], 16;" :: "r"(dst), "l"(src) : "memory");
}
#define CP_COMMIT() asm volatile("cp.async.commit_group;" ::: "memory")
#define CP_WAIT2()  asm volatile("cp.async.wait_group 2;" ::: "memory")
#define CP_WAIT0()  asm volatile("cp.async.wait_group 0;" ::: "memory")

__device__ __forceinline__ void ldsm4(uint32_t* r, uint32_t addr) {
    asm volatile("ldmatrix.sync.aligned.m8n8.x4.shared.b16 {%0,%1,%2,%3}, [%4];"
                 : "=r"(r[0]), "=r"(r[1]), "=r"(r[2]), "=r"(r[3]) : "r"(addr));
}
__device__ __forceinline__ void mma16816(float* c, const uint32_t* a, const uint32_t* b) {
    asm volatile(
        "mma.sync.aligned.m16n8k16.row.col.f32.f16.f16.f32 "
        "{%0,%1,%2,%3}, {%4,%5,%6,%7}, {%8,%9}, {%0,%1,%2,%3};"
        : "+f"(c[0]), "+f"(c[1]), "+f"(c[2]), "+f"(c[3])
        : "r"(a[0]), "r"(a[1]), "r"(a[2]), "r"(a[3]), "r"(b[0]), "r"(b[1]));
}

// ---------------- 1. h1 -----------------------------------------------------
__global__ void k_h1(const float* __restrict__ x,
                     const float* __restrict__ fc0w,
                     const float* __restrict__ fc0b) {
    int idx = blockIdx.x * 256 + threadIdx.x;
    float acc = fc0b[0];
    const float* xr = x + (size_t)idx * SS;
#pragma unroll
    for (int s = 0; s < SS; ++s) acc = fmaf(xr[s], fc0w[s], acc);
    g_h1[idx] = tanhf(acc);
}

// ---------------- 2. h2 -----------------------------------------------------
__global__ void k_h2(const float* __restrict__ fc1w,
                     const float* __restrict__ fc1b) {
    int i = blockIdx.x >> 4;
    int d = blockIdx.x & 15;
    int tid = threadIdx.x;
    float p = 0.f;
    for (int n = tid; n < NN; n += 256)
        p = fmaf(g_h1[i * NN + n], fc1w[d * NN + n], p);
    __shared__ float red[256];
    red[tid] = p; __syncthreads();
    for (int st = 128; st > 0; st >>= 1) {
        if (tid < st) red[tid] += red[tid + st];
        __syncthreads();
    }
    if (tid == 0) g_h2[i * EE + d] = tanhf(red[0] + fc1b[d]);
}

// ---------------- 3. m ------------------------------------------------------
__global__ void k_m(const float* __restrict__ fc2w,
                    const float* __restrict__ fc2b) {
    int t = threadIdx.x;
    int d = t >> 4, e = t & 15;
    float acc = fc2b[e];
#pragma unroll
    for (int i = 0; i < II; ++i) acc = fmaf(g_h2[i * EE + d], fc2w[e * II + i], acc);
    g_m[d * EE + e] = tanhf(acc);
}

// ------- 4. adjacency softmax -> fp16 (warp-per-row) ------------------------
__global__ __launch_bounds__(128) void k_adj(const float* __restrict__ E1,
                                             const float* __restrict__ E2) {
    __shared__ float buf[4][NN];
    int w = threadIdx.x >> 5, lane = threadIdx.x & 31;
    int n = blockIdx.x * 4 + w;

    float pv = 0.f;
    if (lane < EE) {
#pragma unroll
        for (int d = 0; d < EE; ++d) pv = fmaf(E1[n * EE + d], g_m[d * EE + lane], pv);
    }
    float pl[EE];
#pragma unroll
    for (int e = 0; e < EE; ++e) pl[e] = __shfl_sync(0xffffffffu, pv, e);

    float lmax = 0.f;   // relu => logits >= 0
    for (int mc = lane; mc < NN; mc += 32) {
        const float4* er = (const float4*)(E2 + mc * EE);
        float4 q0 = er[0], q1 = er[1], q2 = er[2], q3 = er[3];
        float a = 0.f;
        a = fmaf(pl[0], q0.x, a);  a = fmaf(pl[1], q0.y, a);
        a = fmaf(pl[2], q0.z, a);  a = fmaf(pl[3], q0.w, a);
        a = fmaf(pl[4], q1.x, a);  a = fmaf(pl[5], q1.y, a);
        a = fmaf(pl[6], q1.z, a);  a = fmaf(pl[7], q1.w, a);
        a = fmaf(pl[8], q2.x, a);  a = fmaf(pl[9], q2.y, a);
        a = fmaf(pl[10], q2.z, a); a = fmaf(pl[11], q2.w, a);
        a = fmaf(pl[12], q3.x, a); a = fmaf(pl[13], q3.y, a);
        a = fmaf(pl[14], q3.z, a); a = fmaf(pl[15], q3.w, a);
        a = fmaxf(a, 0.f);
        buf[w][mc] = a;
        lmax = fmaxf(lmax, a);
    }
#pragma unroll
    for (int o = 16; o; o >>= 1) lmax = fmaxf(lmax, __shfl_xor_sync(0xffffffffu, lmax, o));

    float lsum = 0.f;
    for (int mc = lane; mc < NN; mc += 32) {
        float v = __expf(buf[w][mc] - lmax);
        buf[w][mc] = v;
        lsum += v;
    }
#pragma unroll
    for (int o = 16; o; o >>= 1) lsum += __shfl_xor_sync(0xffffffffu, lsum, o);
    float inv = 1.0f / lsum;

    for (int mc = lane; mc < NN; mc += 32)
        g_Ah[(size_t)n * NN + mc] = __float2half_rn(buf[w][mc] * inv);
}

// --------- 5. B0h = fp16(x^T):  B0[(b,i,s)][m] = x[b,i,m,s] ----------------
__global__ __launch_bounds__(256) void k_split0(const float* __restrict__ x) {
    int bi = blockIdx.x;
    int m = blockIdx.y * 256 + threadIdx.x;
    const float* src = x + ((size_t)bi * NN + m) * SS;
    float v[SS];
#pragma unroll
    for (int s = 0; s < SS; ++s) v[s] = src[s];
#pragma unroll
    for (int s = 0; s < SS; ++s)
        g_B0h[(size_t)(bi * SS + s) * NN + m] = __float2half_rn(v[s]);
}

// ============== GEMM core defs ==============================================
// BM=128, BN=192, BK=32; warp tile 64x48 (8 warps = 2m x 4n); grid 16x64=1024
#define ROWB 80
#define MATSZ_A (128 * ROWB)    // 10240
#define MATSZ_B (192 * ROWB)    // 15360
#define STG   (MATSZ_A + MATSZ_B)   // 25600
#define NSTG  4
#define SMTOT (NSTG * STG)      // 102400
#define NCHUNK (NN / 32)
#define ROWP 132                // fp16 transpose-staging row pitch

// common GEMM body: computes acc for one 128x192 tile of C = Ah @ B^T
#define GEMM_BODY(pB)                                                           \
    const char* pAh = (const char*)g_Ah;                                        \
    const char* pBh = (const char*)(pB);                                        \
    const int m0 = blockIdx.x * 128;                                            \
    const int c0 = blockIdx.y * 192;                                            \
    auto load_stage = [&](int stg, int chunk) {                                 \
        const uint32_t base = sb + stg * STG;                                   \
        const int k0 = chunk * 32;                                              \
        _Pragma("unroll")                                                       \
        for (int r = 0; r < 5; ++r) {                                           \
            int id = tid + r * 256;                                             \
            if (id < 512) {                                                     \
                int row = id >> 2, cc = id & 3;                                 \
                cp16(base + row * ROWB + cc * 16,                               \
                     pAh + ((size_t)(m0 + row) * NN + k0 + cc * 8) * 2);        \
            } else {                                                            \
                int idx = id - 512;                                             \
                int row = idx >> 2, cc = idx & 3;                               \
                cp16(base + MATSZ_A + row * ROWB + cc * 16,                     \
                     pBh + ((size_t)(c0 + row) * NN + k0 + cc * 8) * 2);        \
            }                                                                   \
        }                                                                       \
    };                                                                          \
    float acc[4][6][4];                                                         \
    _Pragma("unroll")                                                           \
    for (int i = 0; i < 4; ++i)                                                 \
        _Pragma("unroll")                                                       \
        for (int j = 0; j < 6; ++j)                                             \
            _Pragma("unroll")                                                   \
            for (int q = 0; q < 4; ++q) acc[i][j][q] = 0.f;                     \
    load_stage(0, 0); CP_COMMIT();                                              \
    load_stage(1, 1); CP_COMMIT();                                              \
    load_stage(2, 2); CP_COMMIT();                                              \
    const int grp = lane >> 3, lr = lane & 7;                                   \
    const int a_row_base = m_off + (grp & 1) * 8 + lr;                          \
    const int a_kc = grp >> 1;                                                  \
    const int b_row_base = n_off + (grp >> 1) * 8 + lr;                         \
    const int b_kc = grp & 1;                                                   \
    for (int c = 0; c < NCHUNK; ++c) {                                          \
        const int st = c & 3;                                                   \
        if (c + 1 < NCHUNK) CP_WAIT2(); else CP_WAIT0();                        \
        __syncthreads();                                                        \
        if (c + 3 < NCHUNK) load_stage((c + 3) & 3, c + 3);                     \
        CP_COMMIT();                                                            \
        const uint32_t base = sb + st * STG;                                    \
        _Pragma("unroll")                                                       \
        for (int ks = 0; ks < 2; ++ks) {                                        \
            const int kc0 = ks * 2;                                             \
            uint32_t ah[4][4], bh[3][4];                                        \
            _Pragma("unroll")                                                   \
            for (int mf = 0; mf < 4; ++mf)                                      \
                ldsm4(ah[mf], base + (a_row_base + mf * 16) * ROWB              \
                                  + (a_kc + kc0) * 16);                         \
            _Pragma("unroll")                                                   \
            for (int nf = 0; nf < 3; ++nf)                                      \
                ldsm4(bh[nf], base + MATSZ_A + (b_row_base + nf * 16) * ROWB    \
                                  + (b_kc + kc0) * 16);                         \
            _Pragma("unroll")                                                   \
            for (int mf = 0; mf < 4; ++mf)                                      \
                _Pragma("unroll")                                               \
                for (int nf = 0; nf < 3; ++nf) {                                \
                    mma16816(acc[mf][nf * 2],     ah[mf], &bh[nf][0]);          \
                    mma16816(acc[mf][nf * 2 + 1], ah[mf], &bh[nf][2]);          \
                }                                                               \
        }                                                                       \
    }

// ============== 6a. GEMM1  Y1 = S @ X  -> Y1h + fused B1h transpose =========
__global__ __launch_bounds__(256, 1) void k_mma1() {
    extern __shared__ char smem[];
    const uint32_t sb = smem_u32(smem);
    const int tid = threadIdx.x;
    const int lane = tid & 31;
    const int warp = tid >> 5;
    const int m_off = (warp & 1) * 64;
    const int n_off = (warp >> 1) * 48;

    GEMM_BODY(g_B0h)

    __syncthreads();
    // g_Y1h [row][col]
#pragma unroll
    for (int mf = 0; mf < 4; ++mf) {
#pragma unroll
        for (int half = 0; half < 2; ++half) {
            int rowL = m_off + mf * 16 + half * 8 + (lane >> 2);
            __half* yr = g_Y1h + (size_t)(m0 + rowL) * BIS + c0;
#pragma unroll
            for (int n8 = 0; n8 < 6; ++n8) {
                int colL = n_off + n8 * 8 + (lane & 3) * 2;
                __half h0 = __float2half_rn(acc[mf][n8][half * 2]);
                __half h1 = __float2half_rn(acc[mf][n8][half * 2 + 1]);
                *(__half2*)(yr + colL) = __halves2half2(h0, h1);
            }
        }
    }
    // two-pass smem transpose (96 cols each) -> g_B1h [col][row]
    __half* sh = (__half*)smem;
#pragma unroll
    for (int p = 0; p < 2; ++p) {
        __syncthreads();
        if (n_off >= p * 96 && n_off < p * 96 + 96) {
#pragma unroll
            for (int mf = 0; mf < 4; ++mf) {
#pragma unroll
                for (int half = 0; half < 2; ++half) {
                    int rowL = m_off + mf * 16 + half * 8 + (lane >> 2);
#pragma unroll
                    for (int n8 = 0; n8 < 6; ++n8) {
                        int colL = n_off + n8 * 8 + (lane & 3) * 2 - p * 96;
                        sh[colL * ROWP + rowL] =
                            __float2half_rn(acc[mf][n8][half * 2]);
                        sh[(colL + 1) * ROWP + rowL] =
                            __float2half_rn(acc[mf][n8][half * 2 + 1]);
                    }
                }
            }
        }
        __syncthreads();
        int col = tid >> 1, rh = tid & 1;
        if (col < 96) {
            const __half* srow = sh + col * ROWP + rh * 64;
            __half* drow = g_B1h + (size_t)(c0 + p * 96 + col) * NN + m0 + rh * 64;
#pragma unroll
            for (int q = 0; q < 16; ++q)
                *(uint2*)(drow + q * 4) = *(const uint2*)(srow + q * 4);
        }
    }
}

// ============== 6b. GEMM2  Y2 = S @ Y1  -> Y2h ==============================
__global__ __launch_bounds__(256, 1) void k_mma2() {
    extern __shared__ char smem[];
    const uint32_t sb = smem_u32(smem);
    const int tid = threadIdx.x;
    const int lane = tid & 31;
    const int warp = tid >> 5;
    const int m_off = (warp & 1) * 64;
    const int n_off = (warp >> 1) * 48;

    GEMM_BODY(g_B1h)

#pragma unroll
    for (int mf = 0; mf < 4; ++mf) {
#pragma unroll
        for (int half = 0; half < 2; ++half) {
            int rowL = m_off + mf * 16 + half * 8 + (lane >> 2);
            __half* yr = g_Y2h + (size_t)(m0 + rowL) * BIS + c0;
#pragma unroll
            for (int n8 = 0; n8 < 6; ++n8) {
                int colL = n_off + n8 * 8 + (lane & 3) * 2;
                __half h0 = __float2half_rn(acc[mf][n8][half * 2]);
                __half h1 = __float2half_rn(acc[mf][n8][half * 2 + 1]);
                *(__half2*)(yr + colL) = __halves2half2(h0, h1);
            }
        }
    }
}

// ---------------- 7. per-node generated weights + bias ----------------------
__global__ void k_weights(const float* __restrict__ E1, const float* __restrict__ E2,
                          const float* __restrict__ Wp, const float* __restrict__ Wp2,
                          const float* __restrict__ bp, const float* __restrict__ bp2) {
    int n = blockIdx.x, tid = threadIdx.x;
    __shared__ float e1[EE], e2[EE];
    if (tid < EE) e1[tid] = E1[n * EE + tid];
    else if (tid < 2 * EE) e2[tid - EE] = E2[n * EE + tid - EE];
    __syncthreads();
    float l1[EE], l2[EE];
#pragma unroll
    for (int d = 0; d < EE; ++d) { l1[d] = e1[d]; l2[d] = e2[d]; }
    for (int q = tid; q < PW; q += 256) {
        float acc = 0.f;
#pragma unroll
        for (int d = 0; d < EE; ++d)
            acc = fmaf(l1[d], Wp[d * PW + q], fmaf(l2[d], Wp2[d * PW + q], acc));
        g_W[(size_t)n * PW + q] = acc;
    }
    if (tid < OO) {
        float acc = 0.f;
#pragma unroll
        for (int d = 0; d < EE; ++d)
            acc = fmaf(l1[d], bp[d * OO + tid], fmaf(l2[d], bp2[d * OO + tid], acc));
        g_bias[n * OO + tid] = acc;
    }
}

// -------- 8. gconv (hop0 from x fp32; hops 1,2 from fp16) -------------------
__global__ __launch_bounds__(384) void k_gconv(const float* __restrict__ x,
                                               float* __restrict__ out) {
    int n = blockIdx.x, tid = threadIdx.x;
    __shared__ float Ws[PW];
    __shared__ float bsh[OO];
    for (int q = tid; q < PW; q += 384) Ws[q] = g_W[(size_t)n * PW + q];
    if (tid < OO) bsh[tid] = g_bias[n * OO + tid];
    __syncthreads();
    int b = tid / SS, s = tid - b * SS;
    float acc[OO];
#pragma unroll
    for (int o = 0; o < OO; ++o) acc[o] = bsh[o];

    // hop 0: x[b,i,n,s] fp32
    {
        const float* yb = x + ((size_t)(b * II) * NN + n) * SS + s;
        const float* wk = Ws;
#pragma unroll 4
        for (int i = 0; i < II; ++i) {
            float v = yb[(size_t)i * NN * SS];
            const float* wr = wk + i * OO;
#pragma unroll
            for (int o = 0; o < OO; ++o) acc[o] = fmaf(v, wr[o], acc[o]);
        }
    }
    // hops 1,2: Y1h, Y2h [n][(b,i,s)] fp16
    const __half* Yb[2] = { g_Y1h, g_Y2h };
#pragma unroll
    for (int k = 0; k < 2; ++k) {
        const __half* yb = Yb[k] + (size_t)n * BIS + (size_t)b * II * SS + s;
        const float* wk = Ws + (k + 1) * II * OO;
#pragma unroll 4
        for (int i = 0; i < II; ++i) {
            float v = __half2float(yb[i * SS]);
            const float* wr = wk + i * OO;
#pragma unroll
            for (int o = 0; o < OO; ++o) acc[o] = fmaf(v, wr[o], acc[o]);
        }
    }
#pragma unroll
    for (int o = 0; o < OO; ++o)
        out[(((size_t)b * OO + o) * NN + n) * SS + s] = acc[o];
}

// ---------------------------------------------------------------------------
extern "C" void kernel_launch(void* const* d_in, const int* in_sizes, int n_in,
                              void* d_out, int out_size) {
    const float* x    = (const float*)d_in[0];
    const float* E1   = (const float*)d_in[1];
    const float* E2   = (const float*)d_in[2];
    const float* Wp   = (const float*)d_in[3];
    const float* Wp2  = (const float*)d_in[4];
    const float* bp   = (const float*)d_in[5];
    const float* bp2  = (const float*)d_in[6];
    const float* fc0w = (const float*)d_in[7];
    const float* fc0b = (const float*)d_in[8];
    const float* fc1w = (const float*)d_in[9];
    const float* fc1b = (const float*)d_in[10];
    const float* fc2w = (const float*)d_in[11];
    const float* fc2b = (const float*)d_in[12];
    float* out = (float*)d_out;

    cudaFuncSetAttribute(k_mma1, cudaFuncAttributeMaxDynamicSharedMemorySize, SMTOT);
    cudaFuncSetAttribute(k_mma2, cudaFuncAttributeMaxDynamicSharedMemorySize, SMTOT);

    k_h1<<<II * NN / 256, 256>>>(x, fc0w, fc0b);
    k_h2<<<II * EE, 256>>>(fc1w, fc1b);
    k_m<<<1, 256>>>(fc2w, fc2b);
    k_adj<<<NN / 4, 128>>>(E1, E2);

    k_split0<<<dim3(BB * II, NN / 256), 256>>>(x);     // x -> B0h

    dim3 gg(NN / 128, BIS / 192);
    k_mma1<<<gg, 256, SMTOT>>>();                      // Y1h + B1h (fused)
    k_mma2<<<gg, 256, SMTOT>>>();                      // Y2h

    k_weights<<<NN, 256>>>(E1, E2, Wp, Wp2, bp, bp2);
    k_gconv<<<NN, 384>>>(x, out);
}

// round 14
// speedup vs baseline: 5.4418x; 1.1147x over previous
#include <cuda_runtime.h>
#include <cuda_fp16.h>
#include <cstdint>

#define NN   2048
#define BB   32
#define II   32
#define OO   32
#define SS   12
#define EE   16
#define KK   3          // K+1 hops
#define BIS  12288      // B*II*SS
#define PW   (KK*II*OO)

// ---------------- scratch (device globals) ----------------------------------
__device__ float g_h1[II * NN];
__device__ float g_h2[II * EE];
__device__ float g_m[EE * EE];
__device__ float g_W[(size_t)NN * PW];
__device__ float g_bias[NN * OO];
// fp16 operands / results
__device__ __align__(16) __half g_Ah[(size_t)NN * NN];    // S        [n][k]
__device__ __align__(16) __half g_B0h[(size_t)BIS * NN];  // X^T      [col][k]
__device__ __align__(16) __half g_B1h[(size_t)BIS * NN];  // Y1^T     [col][k]
__device__ __align__(16) __half g_Y1h[(size_t)NN * BIS];  // Y1       [n][col]
__device__ __align__(16) __half g_Y2h[(size_t)NN * BIS];  // Y2       [n][col]

// ---------------- helpers ----------------------------------------------------
__device__ __forceinline__ uint32_t smem_u32(const void* p) {
    uint32_t a;
    asm("{ .reg .u64 t; cvta.to.shared.u64 t, %1; cvt.u32.u64 %0, t; }" : "=r"(a) : "l"(p));
    return a;
}
__device__ __forceinline__ void cp16(uint32_t dst, const void* src) {
    asm volatile("cp.async.cg.shared.global [%0], [%1], 16;" :: "r"(dst), "l"(src) : "memory");
}
#define CP_COMMIT() asm volatile("cp.async.commit_group;" ::: "memory")
#define CP_WAIT2()  asm volatile("cp.async.wait_group 2;" ::: "memory")
#define CP_WAIT0()  asm volatile("cp.async.wait_group 0;" ::: "memory")

__device__ __forceinline__ void ldsm4(uint32_t* r, uint32_t addr) {
    asm volatile("ldmatrix.sync.aligned.m8n8.x4.shared.b16 {%0,%1,%2,%3}, [%4];"
                 : "=r"(r[0]), "=r"(r[1]), "=r"(r[2]), "=r"(r[3]) : "r"(addr));
}
__device__ __forceinline__ void mma16816(float* c, const uint32_t* a, const uint32_t* b) {
    asm volatile(
        "mma.sync.aligned.m16n8k16.row.col.f32.f16.f16.f32 "
        "{%0,%1,%2,%3}, {%4,%5,%6,%7}, {%8,%9}, {%0,%1,%2,%3};"
        : "+f"(c[0]), "+f"(c[1]), "+f"(c[2]), "+f"(c[3])
        : "r"(a[0]), "r"(a[1]), "r"(a[2]), "r"(a[3]), "r"(b[0]), "r"(b[1]));
}
// packed fp32x2 FMA (base Blackwell PTX; per-lane IEEE fma)
__device__ __forceinline__ void ffma2(unsigned long long& c,
                                      unsigned long long a, unsigned long long b) {
    asm("fma.rn.f32x2 %0, %1, %2, %0;" : "+l"(c) : "l"(a), "l"(b));
}
__device__ __forceinline__ unsigned long long pk2(float lo, float hi) {
    unsigned long long r;
    asm("mov.b64 %0, {%1, %2};" : "=l"(r) : "f"(lo), "f"(hi));
    return r;
}
__device__ __forceinline__ void upk2(float& lo, float& hi, unsigned long long v) {
    asm("mov.b64 {%0, %1}, %2;" : "=f"(lo), "=f"(hi) : "l"(v));
}

// ---------------- 1. h1 -----------------------------------------------------
__global__ void k_h1(const float* __restrict__ x,
                     const float* __restrict__ fc0w,
                     const float* __restrict__ fc0b) {
    int idx = blockIdx.x * 256 + threadIdx.x;
    float acc = fc0b[0];
    const float* xr = x + (size_t)idx * SS;
#pragma unroll
    for (int s = 0; s < SS; ++s) acc = fmaf(xr[s], fc0w[s], acc);
    g_h1[idx] = tanhf(acc);
}

// ---------------- 2. h2 -----------------------------------------------------
__global__ void k_h2(const float* __restrict__ fc1w,
                     const float* __restrict__ fc1b) {
    int i = blockIdx.x >> 4;
    int d = blockIdx.x & 15;
    int tid = threadIdx.x;
    float p = 0.f;
    for (int n = tid; n < NN; n += 256)
        p = fmaf(g_h1[i * NN + n], fc1w[d * NN + n], p);
    __shared__ float red[256];
    red[tid] = p; __syncthreads();
    for (int st = 128; st > 0; st >>= 1) {
        if (tid < st) red[tid] += red[tid + st];
        __syncthreads();
    }
    if (tid == 0) g_h2[i * EE + d] = tanhf(red[0] + fc1b[d]);
}

// ---------------- 3. m ------------------------------------------------------
__global__ void k_m(const float* __restrict__ fc2w,
                    const float* __restrict__ fc2b) {
    int t = threadIdx.x;
    int d = t >> 4, e = t & 15;
    float acc = fc2b[e];
#pragma unroll
    for (int i = 0; i < II; ++i) acc = fmaf(g_h2[i * EE + d], fc2w[e * II + i], acc);
    g_m[d * EE + e] = tanhf(acc);
}

// ------- 4. adjacency softmax -> fp16 (block-per-row, 128 thr) --------------
__global__ __launch_bounds__(128) void k_adj(const float* __restrict__ E1,
                                             const float* __restrict__ E2) {
    __shared__ float buf[NN];         // 8 KB
    __shared__ float psh[EE];
    __shared__ float red[4];
    int tid = threadIdx.x, lane = tid & 31, w = tid >> 5;
    int n = blockIdx.x;

    if (tid < EE) {
        float a = 0.f;
#pragma unroll
        for (int d = 0; d < EE; ++d) a = fmaf(E1[n * EE + d], g_m[d * EE + tid], a);
        psh[tid] = a;
    }
    __syncthreads();
    float pl[EE];
#pragma unroll
    for (int e = 0; e < EE; ++e) pl[e] = psh[e];

    float lmax = 0.f;   // relu => logits >= 0
#pragma unroll
    for (int it = 0; it < NN / 128; ++it) {
        int mc = it * 128 + tid;
        const float4* er = (const float4*)(E2 + mc * EE);
        float4 q0 = er[0], q1 = er[1], q2 = er[2], q3 = er[3];
        float a = 0.f;
        a = fmaf(pl[0], q0.x, a);  a = fmaf(pl[1], q0.y, a);
        a = fmaf(pl[2], q0.z, a);  a = fmaf(pl[3], q0.w, a);
        a = fmaf(pl[4], q1.x, a);  a = fmaf(pl[5], q1.y, a);
        a = fmaf(pl[6], q1.z, a);  a = fmaf(pl[7], q1.w, a);
        a = fmaf(pl[8], q2.x, a);  a = fmaf(pl[9], q2.y, a);
        a = fmaf(pl[10], q2.z, a); a = fmaf(pl[11], q2.w, a);
        a = fmaf(pl[12], q3.x, a); a = fmaf(pl[13], q3.y, a);
        a = fmaf(pl[14], q3.z, a); a = fmaf(pl[15], q3.w, a);
        a = fmaxf(a, 0.f);
        buf[mc] = a;
        lmax = fmaxf(lmax, a);
    }
#pragma unroll
    for (int o = 16; o; o >>= 1) lmax = fmaxf(lmax, __shfl_xor_sync(0xffffffffu, lmax, o));
    if (lane == 0) red[w] = lmax;
    __syncthreads();
    lmax = fmaxf(fmaxf(red[0], red[1]), fmaxf(red[2], red[3]));

    float lsum = 0.f;
#pragma unroll
    for (int it = 0; it < NN / 128; ++it) {
        int mc = it * 128 + tid;
        float v = __expf(buf[mc] - lmax);
        buf[mc] = v;
        lsum += v;
    }
#pragma unroll
    for (int o = 16; o; o >>= 1) lsum += __shfl_xor_sync(0xffffffffu, lsum, o);
    __syncthreads();               // red reuse
    if (lane == 0) red[w] = lsum;
    __syncthreads();
    float inv = 1.0f / (red[0] + red[1] + red[2] + red[3]);

#pragma unroll
    for (int it = 0; it < NN / 128; ++it) {
        int mc = it * 128 + tid;
        g_Ah[(size_t)n * NN + mc] = __float2half_rn(buf[mc] * inv);
    }
}

// --------- 5. B0h = fp16(x^T):  B0[(b,i,s)][m] = x[b,i,m,s] ----------------
__global__ __launch_bounds__(256) void k_split0(const float* __restrict__ x) {
    int bi = blockIdx.x;
    int m = blockIdx.y * 256 + threadIdx.x;
    const float* src = x + ((size_t)bi * NN + m) * SS;
    float v[SS];
#pragma unroll
    for (int s = 0; s < SS; ++s) v[s] = src[s];
#pragma unroll
    for (int s = 0; s < SS; ++s)
        g_B0h[(size_t)(bi * SS + s) * NN + m] = __float2half_rn(v[s]);
}

// ============== GEMM core defs ==============================================
// BM=128, BN=192, BK=64; warp tile 64x48 (8 warps = 2m x 4n); grid 16x64=1024
#define ROWB 144
#define MATSZ_A (128 * ROWB)    // 18432
#define MATSZ_B (192 * ROWB)    // 27648
#define STG   (MATSZ_A + MATSZ_B)   // 46080
#define NSTG  4
#define SMTOT (NSTG * STG)      // 184320
#define NCHUNK (NN / 64)        // 32
#define ROWP 132                // fp16 transpose-staging row pitch

// common GEMM body: computes acc for one 128x192 tile of C = Ah @ B^T
#define GEMM_BODY(pB)                                                           \
    const char* pAh = (const char*)g_Ah;                                        \
    const char* pBh = (const char*)(pB);                                        \
    const int m0 = blockIdx.x * 128;                                            \
    const int c0 = blockIdx.y * 192;                                            \
    auto load_stage = [&](int stg, int chunk) {                                 \
        const uint32_t base = sb + stg * STG;                                   \
        const int k0 = chunk * 64;                                              \
        _Pragma("unroll")                                                       \
        for (int r = 0; r < 10; ++r) {                                          \
            int id = tid + r * 256;                                             \
            if (id < 1024) {                                                    \
                int row = id >> 3, cc = id & 7;                                 \
                cp16(base + row * ROWB + cc * 16,                               \
                     pAh + ((size_t)(m0 + row) * NN + k0 + cc * 8) * 2);        \
            } else {                                                            \
                int idx = id - 1024;                                            \
                int row = idx >> 3, cc = idx & 7;                               \
                cp16(base + MATSZ_A + row * ROWB + cc * 16,                     \
                     pBh + ((size_t)(c0 + row) * NN + k0 + cc * 8) * 2);        \
            }                                                                   \
        }                                                                       \
    };                                                                          \
    float acc[4][6][4];                                                         \
    _Pragma("unroll")                                                           \
    for (int i = 0; i < 4; ++i)                                                 \
        _Pragma("unroll")                                                       \
        for (int j = 0; j < 6; ++j)                                             \
            _Pragma("unroll")                                                   \
            for (int q = 0; q < 4; ++q) acc[i][j][q] = 0.f;                     \
    load_stage(0, 0); CP_COMMIT();                                              \
    load_stage(1, 1); CP_COMMIT();                                              \
    load_stage(2, 2); CP_COMMIT();                                              \
    const int grp = lane >> 3, lr = lane & 7;                                   \
    const int a_row_base = m_off + (grp & 1) * 8 + lr;                          \
    const int a_kc = grp >> 1;                                                  \
    const int b_row_base = n_off + (grp >> 1) * 8 + lr;                         \
    const int b_kc = grp & 1;                                                   \
    for (int c = 0; c < NCHUNK; ++c) {                                          \
        const int st = c & 3;                                                   \
        if (c + 1 < NCHUNK) CP_WAIT2(); else CP_WAIT0();                        \
        __syncthreads();                                                        \
        if (c + 3 < NCHUNK) load_stage((c + 3) & 3, c + 3);                     \
        CP_COMMIT();                                                            \
        const uint32_t base = sb + st * STG;                                    \
        _Pragma("unroll")                                                       \
        for (int ks = 0; ks < 4; ++ks) {                                        \
            const int kc0 = ks * 2;                                             \
            uint32_t ah[4][4], bh[3][4];                                        \
            _Pragma("unroll")                                                   \
            for (int mf = 0; mf < 4; ++mf)                                      \
                ldsm4(ah[mf], base + (a_row_base + mf * 16) * ROWB              \
                                  + (a_kc + kc0) * 16);                         \
            _Pragma("unroll")                                                   \
            for (int nf = 0; nf < 3; ++nf)                                      \
                ldsm4(bh[nf], base + MATSZ_A + (b_row_base + nf * 16) * ROWB    \
                                  + (b_kc + kc0) * 16);                         \
            _Pragma("unroll")                                                   \
            for (int mf = 0; mf < 4; ++mf)                                      \
                _Pragma("unroll")                                               \
                for (int nf = 0; nf < 3; ++nf) {                                \
                    mma16816(acc[mf][nf * 2],     ah[mf], &bh[nf][0]);          \
                    mma16816(acc[mf][nf * 2 + 1], ah[mf], &bh[nf][2]);          \
                }                                                               \
        }                                                                       \
    }

// ============== 6a. GEMM1  Y1 = S @ X  -> Y1h + fused B1h transpose =========
__global__ __launch_bounds__(256, 1) void k_mma1() {
    extern __shared__ char smem[];
    const uint32_t sb = smem_u32(smem);
    const int tid = threadIdx.x;
    const int lane = tid & 31;
    const int warp = tid >> 5;
    const int m_off = (warp & 1) * 64;
    const int n_off = (warp >> 1) * 48;

    GEMM_BODY(g_B0h)

    __syncthreads();
    // g_Y1h [row][col]
#pragma unroll
    for (int mf = 0; mf < 4; ++mf) {
#pragma unroll
        for (int half = 0; half < 2; ++half) {
            int rowL = m_off + mf * 16 + half * 8 + (lane >> 2);
            __half* yr = g_Y1h + (size_t)(m0 + rowL) * BIS + c0;
#pragma unroll
            for (int n8 = 0; n8 < 6; ++n8) {
                int colL = n_off + n8 * 8 + (lane & 3) * 2;
                __half h0 = __float2half_rn(acc[mf][n8][half * 2]);
                __half h1 = __float2half_rn(acc[mf][n8][half * 2 + 1]);
                *(__half2*)(yr + colL) = __halves2half2(h0, h1);
            }
        }
    }
    // two-pass smem transpose (96 cols each) -> g_B1h [col][row]
    __half* sh = (__half*)smem;
#pragma unroll
    for (int p = 0; p < 2; ++p) {
        __syncthreads();
        if (n_off >= p * 96 && n_off < p * 96 + 96) {
#pragma unroll
            for (int mf = 0; mf < 4; ++mf) {
#pragma unroll
                for (int half = 0; half < 2; ++half) {
                    int rowL = m_off + mf * 16 + half * 8 + (lane >> 2);
#pragma unroll
                    for (int n8 = 0; n8 < 6; ++n8) {
                        int colL = n_off + n8 * 8 + (lane & 3) * 2 - p * 96;
                        sh[colL * ROWP + rowL] =
                            __float2half_rn(acc[mf][n8][half * 2]);
                        sh[(colL + 1) * ROWP + rowL] =
                            __float2half_rn(acc[mf][n8][half * 2 + 1]);
                    }
                }
            }
        }
        __syncthreads();
        int col = tid >> 1, rh = tid & 1;
        if (col < 96) {
            const __half* srow = sh + col * ROWP + rh * 64;
            __half* drow = g_B1h + (size_t)(c0 + p * 96 + col) * NN + m0 + rh * 64;
#pragma unroll
            for (int q = 0; q < 16; ++q)
                *(uint2*)(drow + q * 4) = *(const uint2*)(srow + q * 4);
        }
    }
}

// ============== 6b. GEMM2  Y2 = S @ Y1  -> Y2h ==============================
__global__ __launch_bounds__(256, 1) void k_mma2() {
    extern __shared__ char smem[];
    const uint32_t sb = smem_u32(smem);
    const int tid = threadIdx.x;
    const int lane = tid & 31;
    const int warp = tid >> 5;
    const int m_off = (warp & 1) * 64;
    const int n_off = (warp >> 1) * 48;

    GEMM_BODY(g_B1h)

#pragma unroll
    for (int mf = 0; mf < 4; ++mf) {
#pragma unroll
        for (int half = 0; half < 2; ++half) {
            int rowL = m_off + mf * 16 + half * 8 + (lane >> 2);
            __half* yr = g_Y2h + (size_t)(m0 + rowL) * BIS + c0;
#pragma unroll
            for (int n8 = 0; n8 < 6; ++n8) {
                int colL = n_off + n8 * 8 + (lane & 3) * 2;
                __half h0 = __float2half_rn(acc[mf][n8][half * 2]);
                __half h1 = __float2half_rn(acc[mf][n8][half * 2 + 1]);
                *(__half2*)(yr + colL) = __halves2half2(h0, h1);
            }
        }
    }
}

// ---------------- 7. per-node generated weights + bias ----------------------
__global__ void k_weights(const float* __restrict__ E1, const float* __restrict__ E2,
                          const float* __restrict__ Wp, const float* __restrict__ Wp2,
                          const float* __restrict__ bp, const float* __restrict__ bp2) {
    int n = blockIdx.x, tid = threadIdx.x;
    __shared__ float e1[EE], e2[EE];
    if (tid < EE) e1[tid] = E1[n * EE + tid];
    else if (tid < 2 * EE) e2[tid - EE] = E2[n * EE + tid - EE];
    __syncthreads();
    float l1[EE], l2[EE];
#pragma unroll
    for (int d = 0; d < EE; ++d) { l1[d] = e1[d]; l2[d] = e2[d]; }
    for (int q = tid; q < PW; q += 256) {
        float acc = 0.f;
#pragma unroll
        for (int d = 0; d < EE; ++d)
            acc = fmaf(l1[d], Wp[d * PW + q], fmaf(l2[d], Wp2[d * PW + q], acc));
        g_W[(size_t)n * PW + q] = acc;
    }
    if (tid < OO) {
        float acc = 0.f;
#pragma unroll
        for (int d = 0; d < EE; ++d)
            acc = fmaf(l1[d], bp[d * OO + tid], fmaf(l2[d], bp2[d * OO + tid], acc));
        g_bias[n * OO + tid] = acc;
    }
}

// -------- 8. gconv (f32x2 packed FMA; hop0 x fp32; hops 1,2 fp16) -----------
__global__ __launch_bounds__(384) void k_gconv(const float* __restrict__ x,
                                               float* __restrict__ out) {
    int n = blockIdx.x, tid = threadIdx.x;
    __shared__ __align__(16) float Ws[PW];
    __shared__ float bsh[OO];
    for (int q = tid; q < PW; q += 384) Ws[q] = g_W[(size_t)n * PW + q];
    if (tid < OO) bsh[tid] = g_bias[n * OO + tid];
    __syncthreads();
    int b = tid / SS, s = tid - b * SS;
    unsigned long long acc2[OO / 2];
#pragma unroll
    for (int j = 0; j < OO / 2; ++j) acc2[j] = pk2(bsh[2 * j], bsh[2 * j + 1]);

    // hop 0: x[b,i,n,s] fp32
    {
        const float* yb = x + ((size_t)(b * II) * NN + n) * SS + s;
#pragma unroll 4
        for (int i = 0; i < II; ++i) {
            float v = yb[(size_t)i * NN * SS];
            unsigned long long v2 = pk2(v, v);
            const unsigned long long* wr2 = (const unsigned long long*)(Ws + i * OO);
#pragma unroll
            for (int j = 0; j < OO / 2; ++j) ffma2(acc2[j], v2, wr2[j]);
        }
    }
    // hops 1,2: Y1h, Y2h [n][(b,i,s)] fp16
    const __half* Yb[2] = { g_Y1h, g_Y2h };
#pragma unroll
    for (int k = 0; k < 2; ++k) {
        const __half* yb = Yb[k] + (size_t)n * BIS + (size_t)b * II * SS + s;
        const float* wk = Ws + (k + 1) * II * OO;
#pragma unroll 4
        for (int i = 0; i < II; ++i) {
            float v = __half2float(yb[i * SS]);
            unsigned long long v2 = pk2(v, v);
            const unsigned long long* wr2 = (const unsigned long long*)(wk + i * OO);
#pragma unroll
            for (int j = 0; j < OO / 2; ++j) ffma2(acc2[j], v2, wr2[j]);
        }
    }
#pragma unroll
    for (int j = 0; j < OO / 2; ++j) {
        float lo, hi;
        upk2(lo, hi, acc2[j]);
        out[(((size_t)b * OO + 2 * j) * NN + n) * SS + s] = lo;
        out[(((size_t)b * OO + 2 * j + 1) * NN + n) * SS + s] = hi;
    }
}

// ---------------------------------------------------------------------------
extern "C" void kernel_launch(void* const* d_in, const int* in_sizes, int n_in,
                              void* d_out, int out_size) {
    const float* x    = (const float*)d_in[0];
    const float* E1   = (const float*)d_in[1];
    const float* E2   = (const float*)d_in[2];
    const float* Wp   = (const float*)d_in[3];
    const float* Wp2  = (const float*)d_in[4];
    const float* bp   = (const float*)d_in[5];
    const float* bp2  = (const float*)d_in[6];
    const float* fc0w = (const float*)d_in[7];
    const float* fc0b = (const float*)d_in[8];
    const float* fc1w = (const float*)d_in[9];
    const float* fc1b = (const float*)d_in[10];
    const float* fc2w = (const float*)d_in[11];
    const float* fc2b = (const float*)d_in[12];
    float* out = (float*)d_out;

    cudaFuncSetAttribute(k_mma1, cudaFuncAttributeMaxDynamicSharedMemorySize, SMTOT);
    cudaFuncSetAttribute(k_mma2, cudaFuncAttributeMaxDynamicSharedMemorySize, SMTOT);

    k_h1<<<II * NN / 256, 256>>>(x, fc0w, fc0b);
    k_h2<<<II * EE, 256>>>(fc1w, fc1b);
    k_m<<<1, 256>>>(fc2w, fc2b);
    k_adj<<<NN, 128>>>(E1, E2);

    k_split0<<<dim3(BB * II, NN / 256), 256>>>(x);     // x -> B0h

    dim3 gg(NN / 128, BIS / 192);
    k_mma1<<<gg, 256, SMTOT>>>();                      // Y1h + B1h (fused)
    k_mma2<<<gg, 256, SMTOT>>>();                      // Y2h

    k_weights<<<NN, 256>>>(E1, E2, Wp, Wp2, bp, bp2);
    k_gconv<<<NN, 384>>>(x, out);
}